// round 4
// baseline (speedup 1.0000x reference)
#include <cuda_runtime.h>
#include <math.h>

#define NPTS   32768          // N = B*P
#define BATCH  8
#define PPB    4096           // P
#define KNN    20             // K
#define LCOV   10             // L
#define FDIM   32             // F
#define KSV    5              // KS
#define NCLS   40
#define NROWS  24             // (N*F*3)/(P*F)

// ---------------- scratch (device globals; no allocation allowed) ----------
__device__ int   g_nbr[NPTS * KNN];
__device__ float g_node[NPTS * FDIM];
__device__ float g_v3[NPTS * 3];
__device__ float g_stats[2 * FDIM];      // [0:32) mean, [32:64) invstd
__device__ float g_ys[NROWS * FDIM];

// ======================= K1: brute-force kNN ===============================
// 256 queries per block (one thread per query), candidates tiled via smem.
__global__ __launch_bounds__(256) void knn_kernel(const float* __restrict__ pos) {
    __shared__ float4 spt[256];
    const int tid  = threadIdx.x;
    const int q    = blockIdx.x * 256 + tid;          // global query index
    const int base = (blockIdx.x >> 4) * PPB;         // 16 blocks per batch

    const float qx = pos[q * 3 + 0];
    const float qy = pos[q * 3 + 1];
    const float qz = pos[q * 3 + 2];

    float bd[KNN];
    int   bi[KNN];
#pragma unroll
    for (int i = 0; i < KNN; i++) { bd[i] = __int_as_float(0x7f800000); bi[i] = -1; }
    float worst = __int_as_float(0x7f800000);

    for (int t = 0; t < 16; t++) {
        const int cand = base + t * 256 + tid;
        spt[tid] = make_float4(pos[cand * 3 + 0], pos[cand * 3 + 1], pos[cand * 3 + 2], 0.f);
        __syncthreads();
        const int tbase = base + t * 256;
#pragma unroll 4
        for (int jj = 0; jj < 256; jj++) {
            const float4 c = spt[jj];
            const float dx = qx - c.x, dy = qy - c.y, dz = qz - c.z;
            const float dist = dx * dx + dy * dy + dz * dz;
            const int j = tbase + jj;
            if (dist < worst && j != q) {
                int p = KNN - 1;
                while (p > 0 && bd[p - 1] > dist) {
                    bd[p] = bd[p - 1]; bi[p] = bi[p - 1]; p--;
                }
                bd[p] = dist; bi[p] = j;
                worst = bd[KNN - 1];
            }
        }
        __syncthreads();
    }
#pragma unroll
    for (int i = 0; i < KNN; i++) g_nbr[q * KNN + i] = bi[i];
}

// ======================= K2: geometry + spline conv ========================
__device__ __forceinline__ void power_iter(
    float m00, float m01, float m02, float m11, float m12, float m22,
    float& vx, float& vy, float& vz, float& lam)
{
    vx = vy = vz = 0.57735026918962576f;
#pragma unroll
    for (int it = 0; it < 5; it++) {
        float wx = m00 * vx + m01 * vy + m02 * vz;
        float wy = m01 * vx + m11 * vy + m12 * vz;
        float wz = m02 * vx + m12 * vy + m22 * vz;
        float nr = sqrtf(wx * wx + wy * wy + wz * wz) + 1e-12f;
        vx = wx / nr; vy = wy / nr; vz = wz / nr;
    }
    float wx = m00 * vx + m01 * vy + m02 * vz;
    float wy = m01 * vx + m11 * vy + m12 * vz;
    float wz = m02 * vx + m12 * vy + m22 * vz;
    lam = vx * wx + vy * wy + vz * wz;
}

// warp per point; 8 warps (8 points) per block
__global__ __launch_bounds__(256) void geom_kernel(
    const float* __restrict__ pos, const float* __restrict__ Wsp,
    const float* __restrict__ root, const float* __restrict__ bias)
{
    __shared__ float  wspS[125 * 32];
    __shared__ float  clusS[8][KNN][3];
    __shared__ float2 bfS[8][KNN * 8];     // (basis, flat-as-float)

    const int tid  = threadIdx.x;
    const int w    = tid >> 5;
    const int lane = tid & 31;
    const int n    = blockIdx.x * 8 + w;

    for (int i = tid; i < 125 * 32; i += 256) wspS[i] = Wsp[i];

    const float px = pos[n * 3 + 0];
    const float py = pos[n * 3 + 1];
    const float pz = pos[n * 3 + 2];

    if (lane < KNN) {
        const int j = g_nbr[n * KNN + lane];
        clusS[w][lane][0] = pos[j * 3 + 0] - px;
        clusS[w][lane][1] = pos[j * 3 + 1] - py;
        clusS[w][lane][2] = pos[j * 3 + 2] - pz;
    }
    __syncthreads();   // covers wspS load + cluster writes

    // covariance over first LCOV neighbors (redundant per lane; smem broadcast)
    float m00 = 0, m01 = 0, m02 = 0, m11 = 0, m12 = 0, m22 = 0;
#pragma unroll
    for (int k = 0; k < LCOV; k++) {
        const float x = clusS[w][k][0], y = clusS[w][k][1], z = clusS[w][k][2];
        m00 += x * x; m01 += x * y; m02 += x * z;
        m11 += y * y; m12 += y * z; m22 += z * z;
    }

    float e1x, e1y, e1z, lam1;
    power_iter(m00, m01, m02, m11, m12, m22, e1x, e1y, e1z, lam1);
    // deflate
    float a00 = m00 - lam1 * e1x * e1x;
    float a01 = m01 - lam1 * e1x * e1y;
    float a02 = m02 - lam1 * e1x * e1z;
    float a11 = m11 - lam1 * e1y * e1y;
    float a12 = m12 - lam1 * e1y * e1z;
    float a22 = m22 - lam1 * e1z * e1z;
    float e2x, e2y, e2z, lam2;
    power_iter(a00, a01, a02, a11, a12, a22, e2x, e2y, e2z, lam2);
    // v3 = cross(v1, v2), normalized
    float e3x = e1y * e2z - e1z * e2y;
    float e3y = e1z * e2x - e1x * e2z;
    float e3z = e1x * e2y - e1y * e2x;
    {
        float nr = sqrtf(e3x * e3x + e3y * e3y + e3z * e3z) + 1e-12f;
        e3x /= nr; e3y /= nr; e3z /= nr;
    }

    // pass over all K: sign accumulator and max|dirc|
    float sum2 = 0.f, mx01 = 0.f, mx2 = 0.f;
#pragma unroll
    for (int k = 0; k < KNN; k++) {
        const float x = clusS[w][k][0], y = clusS[w][k][1], z = clusS[w][k][2];
        const float d0 = x * e1x + y * e1y + z * e1z;
        const float d1 = x * e2x + y * e2y + z * e2z;
        const float d2 = x * e3x + y * e3y + z * e3z;
        sum2 += d2;
        mx01 = fmaxf(mx01, fmaxf(fabsf(d0), fabsf(d1)));
        mx2  = fmaxf(mx2, fabsf(d2));
    }
    const float sgn = (sum2 > 0.f) ? 1.f : ((sum2 < 0.f) ? -1.f : 0.f);
    const float mx  = fmaxf(mx01, (sgn != 0.f) ? mx2 : 0.f);

    // spline basis per neighbor (lane k handles neighbor k)
    if (lane < KNN) {
        const float x = clusS[w][lane][0], y = clusS[w][lane][1], z = clusS[w][lane][2];
        const float d0 = x * e1x + y * e1y + z * e1z;
        const float d1 = x * e2x + y * e2y + z * e2z;
        const float d2 = (x * e3x + y * e3y + z * e3z) * sgn;
        const float p0 = d0 / mx * 0.5f + 0.5f;
        const float p1 = d1 / mx * 0.5f + 0.5f;
        const float p2 = d2 / mx * 0.5f + 0.5f;
        const float v0 = p0 * 4.f, v1 = p1 * 4.f, v2 = p2 * 4.f;
        const float f0 = floorf(v0), f1 = floorf(v1), f2 = floorf(v2);
        const float r0 = v0 - f0, r1 = v1 - f1, r2 = v2 - f2;
        const int   i0 = (int)f0, i1 = (int)f1, i2 = (int)f2;
#pragma unroll
        for (int s = 0; s < 8; s++) {
            const int b0 = (s >> 2) & 1, b1v = (s >> 1) & 1, b2v = s & 1;
            const int c0 = min(max(i0 + b0, 0), KSV - 1);
            const int c1 = min(max(i1 + b1v, 0), KSV - 1);
            const int c2 = min(max(i2 + b2v, 0), KSV - 1);
            const float wgt = (b0 ? r0 : 1.f - r0) * (b1v ? r1 : 1.f - r1) * (b2v ? r2 : 1.f - r2);
            const int flat = (c0 * KSV + c1) * KSV + c2;
            bfS[w][lane * 8 + s] = make_float2(wgt, __int_as_float(flat));
        }
    }
    __syncwarp();

    // lane = feature f: accumulate msg over 160 (neighbor,corner) pairs
    float acc = 0.f;
#pragma unroll 8
    for (int e = 0; e < KNN * 8; e++) {
        const float2 t = bfS[w][e];
        acc = fmaf(t.x, wspS[__float_as_int(t.y) * 32 + lane], acc);
    }
    g_node[n * FDIM + lane] = acc / 20.0f + root[lane] + bias[lane];
    if (lane == 0) {
        g_v3[n * 3 + 0] = e3x;
        g_v3[n * 3 + 1] = e3y;
        g_v3[n * 3 + 2] = e3z;
    }
}

// ======================= K3: batchnorm stats (per-feature) =================
__global__ __launch_bounds__(256) void bn_kernel() {
    __shared__ float red[256];
    const int f = blockIdx.x, tid = threadIdx.x;
    float s = 0.f;
    for (int n = tid; n < NPTS; n += 256) s += g_node[n * FDIM + f];
    red[tid] = s; __syncthreads();
    for (int o = 128; o > 0; o >>= 1) { if (tid < o) red[tid] += red[tid + o]; __syncthreads(); }
    const float mean = red[0] / (float)NPTS;
    __syncthreads();
    float s2 = 0.f;
    for (int n = tid; n < NPTS; n += 256) {
        const float d = g_node[n * FDIM + f] - mean;
        s2 += d * d;
    }
    red[tid] = s2; __syncthreads();
    for (int o = 128; o > 0; o >>= 1) { if (tid < o) red[tid] += red[tid + o]; __syncthreads(); }
    if (tid == 0) {
        g_stats[f] = mean;
        g_stats[FDIM + f] = 1.0f / sqrtf(red[0] / (float)NPTS + 1e-5f);
    }
}

// ======================= K4: scrambled sigmoid mean -> ys ==================
// ys[r,f2] = mean_p sigmoid(xb(n,f) * v3(n,c)), with (n,f,c) recovered from
// linear = r*131072 + p*32 + f2  (the torch .view reinterpretation)
__global__ __launch_bounds__(256) void ys_kernel(
    const float* __restrict__ gamma, const float* __restrict__ beta)
{
    __shared__ float red[256];
    const int r = blockIdx.x >> 5;
    const int f2 = blockIdx.x & 31;
    const int tid = threadIdx.x;
    float s = 0.f;
    for (int p = tid; p < PPB; p += 256) {
        const int linear = r * (PPB * FDIM) + p * FDIM + f2;
        const int n   = linear / 96;
        const int rem = linear - n * 96;
        const int f   = rem / 3;
        const int c   = rem - f * 3;
        const float x  = g_node[n * FDIM + f];
        const float xb = gamma[f] * (x - g_stats[f]) * g_stats[FDIM + f] + beta[f];
        const float z  = xb * g_v3[n * 3 + c];
        s += 1.0f / (1.0f + expf(-z));
    }
    red[tid] = s; __syncthreads();
    for (int o = 128; o > 0; o >>= 1) { if (tid < o) red[tid] += red[tid + o]; __syncthreads(); }
    if (tid == 0) g_ys[blockIdx.x] = red[0] / (float)PPB;
}

// ======================= K5: MLP + log_softmax =============================
__global__ __launch_bounds__(256) void mlp_kernel(
    const float* __restrict__ W1, const float* __restrict__ b1,
    const float* __restrict__ W2, const float* __restrict__ b2,
    float* __restrict__ out)
{
    __shared__ float ysS[NROWS * FDIM];
    __shared__ float hS[NROWS * 256];
    __shared__ float lg[NROWS * NCLS];
    const int tid = threadIdx.x;

    for (int i = tid; i < NROWS * FDIM; i += 256) ysS[i] = g_ys[i];
    __syncthreads();

    // hidden layer: thread = hidden unit j
    {
        const int j = tid;
        for (int r = 0; r < NROWS; r++) {
            float a = b1[j];
#pragma unroll
            for (int f = 0; f < FDIM; f++) a = fmaf(ysS[r * FDIM + f], W1[f * 256 + j], a);
            hS[r * 256 + j] = (a > 0.f) ? a : expm1f(a);
        }
    }
    __syncthreads();

    // logits
    for (int o = tid; o < NROWS * NCLS; o += 256) {
        const int r = o / NCLS, k = o - r * NCLS;
        float a = b2[k];
        for (int j = 0; j < 256; j++) a = fmaf(hS[r * 256 + j], W2[j * NCLS + k], a);
        lg[o] = a;
    }
    __syncthreads();

    // log_softmax per row (warp per row, strided)
    const int w = tid >> 5, lane = tid & 31;
    for (int r = w; r < NROWS; r += 8) {
        const float a = lg[r * NCLS + lane];
        const float b = (lane < NCLS - 32) ? lg[r * NCLS + 32 + lane] : -__int_as_float(0x7f800000);
        float m = fmaxf(a, b);
#pragma unroll
        for (int o = 16; o > 0; o >>= 1) m = fmaxf(m, __shfl_xor_sync(0xffffffffu, m, o));
        float s = expf(a - m) + ((lane < NCLS - 32) ? expf(b - m) : 0.f);
#pragma unroll
        for (int o = 16; o > 0; o >>= 1) s += __shfl_xor_sync(0xffffffffu, s, o);
        const float ls = logf(s);
        out[r * NCLS + lane] = a - m - ls;
        if (lane < NCLS - 32) out[r * NCLS + 32 + lane] = b - m - ls;
    }
}

// ======================= launch ============================================
extern "C" void kernel_launch(void* const* d_in, const int* in_sizes, int n_in,
                              void* d_out, int out_size) {
    const float* pos   = (const float*)d_in[0];
    const float* Wsp   = (const float*)d_in[1];
    const float* root  = (const float*)d_in[2];
    const float* bias  = (const float*)d_in[3];
    const float* gamma = (const float*)d_in[4];
    const float* beta  = (const float*)d_in[5];
    const float* W1    = (const float*)d_in[6];
    const float* b1    = (const float*)d_in[7];
    const float* W2    = (const float*)d_in[8];
    const float* b2    = (const float*)d_in[9];
    float* out = (float*)d_out;

    knn_kernel<<<NPTS / 256, 256>>>(pos);
    geom_kernel<<<NPTS / 8, 256>>>(pos, Wsp, root, bias);
    bn_kernel<<<FDIM, 256>>>();
    ys_kernel<<<NROWS * FDIM, 256>>>(gamma, beta);
    mlp_kernel<<<1, 256>>>(W1, b1, W2, b2, out);
}

// round 6
// speedup vs baseline: 3.0987x; 3.0987x over previous
#include <cuda_runtime.h>
#include <math.h>

#define NPTS   32768          // N = B*P
#define BATCH  8
#define PPB    4096           // P
#define KNN    20             // K
#define LCOV   10             // L
#define FDIM   32             // F
#define KSV    5              // KS
#define NCLS   40
#define NROWS  24             // (N*F*3)/(P*F)

// ---------------- scratch (device globals; no allocation allowed) ----------
__device__ int   g_nbr[NPTS * KNN];
__device__ float g_node[NPTS * FDIM];
__device__ float g_v3[NPTS * 3];
__device__ float g_stats[2 * FDIM];      // [0:32) mean, [32:64) invstd
__device__ float g_ys[NROWS * FDIM];

// ======================= K1: brute-force kNN ===============================
// One thread per query; candidates tiled through smem as (x,y,z,|c|^2).
// Distance key s = |c|^2 - 2 q.c  (= d^2 - |q|^2, monotone shift -> same order).
// Self-match has the strictly minimal key (~ -|q|^2), so we keep a 21-deep
// list and drop slot 0 at the end. Insertion is a fully-unrolled predicated
// compare-exchange chain: static indices only => stays in registers.
__global__ __launch_bounds__(256) void knn_kernel(const float* __restrict__ pos) {
    __shared__ float  raw[768];          // coalesced staging (256 pts * 3)
    __shared__ float4 spt[256];
    const int tid  = threadIdx.x;
    const int q    = blockIdx.x * 256 + tid;          // global query index
    const int base = (blockIdx.x >> 4) * PPB;         // 16 blocks per batch

    const float qx = pos[q * 3 + 0];
    const float qy = pos[q * 3 + 1];
    const float qz = pos[q * 3 + 2];

    const float INF = __int_as_float(0x7f800000);
    float bd[KNN + 1];
    int   bi[KNN + 1];
#pragma unroll
    for (int i = 0; i <= KNN; i++) { bd[i] = INF; bi[i] = -1; }
    float worst = INF;

    for (int t = 0; t < 16; t++) {
        // coalesced load of 256 candidate points into smem
        {
            const int src = base * 3 + t * 768;
#pragma unroll
            for (int i = 0; i < 3; i++) raw[tid + i * 256] = pos[src + tid + i * 256];
        }
        __syncthreads();
        {
            const float cx = raw[tid * 3 + 0];
            const float cy = raw[tid * 3 + 1];
            const float cz = raw[tid * 3 + 2];
            spt[tid] = make_float4(cx, cy, cz, cx * cx + cy * cy + cz * cz);
        }
        __syncthreads();

        const int tbase = base + t * 256;
#pragma unroll 2
        for (int jj = 0; jj < 256; jj++) {
            const float4 c = spt[jj];
            const float dot = qx * c.x + qy * c.y + qz * c.z;
            const float s = fmaf(-2.0f, dot, c.w);
            if (s < worst) {
                float d = s; int id = tbase + jj;
#pragma unroll
                for (int i = 0; i <= KNN; i++) {
                    const bool lt = d < bd[i];
                    const float td = bd[i]; const int ti = bi[i];
                    bd[i] = lt ? d  : bd[i];
                    bi[i] = lt ? id : bi[i];
                    d  = lt ? td : d;
                    id = lt ? ti : id;
                }
                worst = bd[KNN];
            }
        }
        __syncthreads();
    }
    // slot 0 is self; emit slots 1..20
#pragma unroll
    for (int i = 0; i < KNN; i++) g_nbr[q * KNN + i] = bi[i + 1];
}

// ======================= K2: geometry + spline conv ========================
__device__ __forceinline__ void power_iter(
    float m00, float m01, float m02, float m11, float m12, float m22,
    float& vx, float& vy, float& vz, float& lam)
{
    vx = vy = vz = 0.57735026918962576f;
#pragma unroll
    for (int it = 0; it < 5; it++) {
        float wx = m00 * vx + m01 * vy + m02 * vz;
        float wy = m01 * vx + m11 * vy + m12 * vz;
        float wz = m02 * vx + m12 * vy + m22 * vz;
        float nr = sqrtf(wx * wx + wy * wy + wz * wz) + 1e-12f;
        vx = wx / nr; vy = wy / nr; vz = wz / nr;
    }
    float wx = m00 * vx + m01 * vy + m02 * vz;
    float wy = m01 * vx + m11 * vy + m12 * vz;
    float wz = m02 * vx + m12 * vy + m22 * vz;
    lam = vx * wx + vy * wy + vz * wz;
}

// warp per point; 8 warps (8 points) per block
__global__ __launch_bounds__(256) void geom_kernel(
    const float* __restrict__ pos, const float* __restrict__ Wsp,
    const float* __restrict__ root, const float* __restrict__ bias)
{
    __shared__ float  wspS[125 * 32];
    __shared__ float  clusS[8][KNN][3];
    __shared__ float2 bfS[8][KNN * 8];     // (basis, flat-as-float)

    const int tid  = threadIdx.x;
    const int w    = tid >> 5;
    const int lane = tid & 31;
    const int n    = blockIdx.x * 8 + w;

    for (int i = tid; i < 125 * 32; i += 256) wspS[i] = Wsp[i];

    const float px = pos[n * 3 + 0];
    const float py = pos[n * 3 + 1];
    const float pz = pos[n * 3 + 2];

    if (lane < KNN) {
        const int j = g_nbr[n * KNN + lane];
        clusS[w][lane][0] = pos[j * 3 + 0] - px;
        clusS[w][lane][1] = pos[j * 3 + 1] - py;
        clusS[w][lane][2] = pos[j * 3 + 2] - pz;
    }
    __syncthreads();   // covers wspS load + cluster writes

    // covariance over first LCOV neighbors (redundant per lane; smem broadcast)
    float m00 = 0, m01 = 0, m02 = 0, m11 = 0, m12 = 0, m22 = 0;
#pragma unroll
    for (int k = 0; k < LCOV; k++) {
        const float x = clusS[w][k][0], y = clusS[w][k][1], z = clusS[w][k][2];
        m00 += x * x; m01 += x * y; m02 += x * z;
        m11 += y * y; m12 += y * z; m22 += z * z;
    }

    float e1x, e1y, e1z, lam1;
    power_iter(m00, m01, m02, m11, m12, m22, e1x, e1y, e1z, lam1);
    // deflate
    float a00 = m00 - lam1 * e1x * e1x;
    float a01 = m01 - lam1 * e1x * e1y;
    float a02 = m02 - lam1 * e1x * e1z;
    float a11 = m11 - lam1 * e1y * e1y;
    float a12 = m12 - lam1 * e1y * e1z;
    float a22 = m22 - lam1 * e1z * e1z;
    float e2x, e2y, e2z, lam2;
    power_iter(a00, a01, a02, a11, a12, a22, e2x, e2y, e2z, lam2);
    // v3 = cross(v1, v2), normalized
    float e3x = e1y * e2z - e1z * e2y;
    float e3y = e1z * e2x - e1x * e2z;
    float e3z = e1x * e2y - e1y * e2x;
    {
        float nr = sqrtf(e3x * e3x + e3y * e3y + e3z * e3z) + 1e-12f;
        e3x /= nr; e3y /= nr; e3z /= nr;
    }

    // pass over all K: sign accumulator and max|dirc|
    float sum2 = 0.f, mx01 = 0.f, mx2 = 0.f;
#pragma unroll
    for (int k = 0; k < KNN; k++) {
        const float x = clusS[w][k][0], y = clusS[w][k][1], z = clusS[w][k][2];
        const float d0 = x * e1x + y * e1y + z * e1z;
        const float d1 = x * e2x + y * e2y + z * e2z;
        const float d2 = x * e3x + y * e3y + z * e3z;
        sum2 += d2;
        mx01 = fmaxf(mx01, fmaxf(fabsf(d0), fabsf(d1)));
        mx2  = fmaxf(mx2, fabsf(d2));
    }
    const float sgn = (sum2 > 0.f) ? 1.f : ((sum2 < 0.f) ? -1.f : 0.f);
    const float mx  = fmaxf(mx01, (sgn != 0.f) ? mx2 : 0.f);

    // spline basis per neighbor (lane k handles neighbor k)
    if (lane < KNN) {
        const float x = clusS[w][lane][0], y = clusS[w][lane][1], z = clusS[w][lane][2];
        const float d0 = x * e1x + y * e1y + z * e1z;
        const float d1 = x * e2x + y * e2y + z * e2z;
        const float d2 = (x * e3x + y * e3y + z * e3z) * sgn;
        const float p0 = d0 / mx * 0.5f + 0.5f;
        const float p1 = d1 / mx * 0.5f + 0.5f;
        const float p2 = d2 / mx * 0.5f + 0.5f;
        const float v0 = p0 * 4.f, v1 = p1 * 4.f, v2 = p2 * 4.f;
        const float f0 = floorf(v0), f1 = floorf(v1), f2 = floorf(v2);
        const float r0 = v0 - f0, r1 = v1 - f1, r2 = v2 - f2;
        const int   i0 = (int)f0, i1 = (int)f1, i2 = (int)f2;
#pragma unroll
        for (int s = 0; s < 8; s++) {
            const int b0 = (s >> 2) & 1, b1v = (s >> 1) & 1, b2v = s & 1;
            const int c0 = min(max(i0 + b0, 0), KSV - 1);
            const int c1 = min(max(i1 + b1v, 0), KSV - 1);
            const int c2 = min(max(i2 + b2v, 0), KSV - 1);
            const float wgt = (b0 ? r0 : 1.f - r0) * (b1v ? r1 : 1.f - r1) * (b2v ? r2 : 1.f - r2);
            const int flat = (c0 * KSV + c1) * KSV + c2;
            bfS[w][lane * 8 + s] = make_float2(wgt, __int_as_float(flat));
        }
    }
    __syncwarp();

    // lane = feature f: accumulate msg over 160 (neighbor,corner) pairs
    float acc = 0.f;
#pragma unroll 8
    for (int e = 0; e < KNN * 8; e++) {
        const float2 t = bfS[w][e];
        acc = fmaf(t.x, wspS[__float_as_int(t.y) * 32 + lane], acc);
    }
    g_node[n * FDIM + lane] = acc / 20.0f + root[lane] + bias[lane];
    if (lane == 0) {
        g_v3[n * 3 + 0] = e3x;
        g_v3[n * 3 + 1] = e3y;
        g_v3[n * 3 + 2] = e3z;
    }
}

// ======================= K3: batchnorm stats (per-feature) =================
__global__ __launch_bounds__(256) void bn_kernel() {
    __shared__ float red[256];
    const int f = blockIdx.x, tid = threadIdx.x;
    float s = 0.f;
    for (int n = tid; n < NPTS; n += 256) s += g_node[n * FDIM + f];
    red[tid] = s; __syncthreads();
    for (int o = 128; o > 0; o >>= 1) { if (tid < o) red[tid] += red[tid + o]; __syncthreads(); }
    const float mean = red[0] / (float)NPTS;
    __syncthreads();
    float s2 = 0.f;
    for (int n = tid; n < NPTS; n += 256) {
        const float d = g_node[n * FDIM + f] - mean;
        s2 += d * d;
    }
    red[tid] = s2; __syncthreads();
    for (int o = 128; o > 0; o >>= 1) { if (tid < o) red[tid] += red[tid + o]; __syncthreads(); }
    if (tid == 0) {
        g_stats[f] = mean;
        g_stats[FDIM + f] = 1.0f / sqrtf(red[0] / (float)NPTS + 1e-5f);
    }
}

// ======================= K4: scrambled sigmoid mean -> ys ==================
// ys[r,f2] = mean_p sigmoid(xb(n,f) * v3(n,c)), with (n,f,c) recovered from
// linear = r*131072 + p*32 + f2  (the torch .view reinterpretation)
__global__ __launch_bounds__(256) void ys_kernel(
    const float* __restrict__ gamma, const float* __restrict__ beta)
{
    __shared__ float red[256];
    const int r = blockIdx.x >> 5;
    const int f2 = blockIdx.x & 31;
    const int tid = threadIdx.x;
    float s = 0.f;
    for (int p = tid; p < PPB; p += 256) {
        const int linear = r * (PPB * FDIM) + p * FDIM + f2;
        const int n   = linear / 96;
        const int rem = linear - n * 96;
        const int f   = rem / 3;
        const int c   = rem - f * 3;
        const float x  = g_node[n * FDIM + f];
        const float xb = gamma[f] * (x - g_stats[f]) * g_stats[FDIM + f] + beta[f];
        const float z  = xb * g_v3[n * 3 + c];
        s += 1.0f / (1.0f + expf(-z));
    }
    red[tid] = s; __syncthreads();
    for (int o = 128; o > 0; o >>= 1) { if (tid < o) red[tid] += red[tid + o]; __syncthreads(); }
    if (tid == 0) g_ys[blockIdx.x] = red[0] / (float)PPB;
}

// ======================= K5: MLP + log_softmax =============================
__global__ __launch_bounds__(256) void mlp_kernel(
    const float* __restrict__ W1, const float* __restrict__ b1,
    const float* __restrict__ W2, const float* __restrict__ b2,
    float* __restrict__ out)
{
    __shared__ float ysS[NROWS * FDIM];
    __shared__ float hS[NROWS * 256];
    __shared__ float lg[NROWS * NCLS];
    const int tid = threadIdx.x;

    for (int i = tid; i < NROWS * FDIM; i += 256) ysS[i] = g_ys[i];
    __syncthreads();

    // hidden layer: thread = hidden unit j
    {
        const int j = tid;
        for (int r = 0; r < NROWS; r++) {
            float a = b1[j];
#pragma unroll
            for (int f = 0; f < FDIM; f++) a = fmaf(ysS[r * FDIM + f], W1[f * 256 + j], a);
            hS[r * 256 + j] = (a > 0.f) ? a : expm1f(a);
        }
    }
    __syncthreads();

    // logits
    for (int o = tid; o < NROWS * NCLS; o += 256) {
        const int r = o / NCLS, k = o - r * NCLS;
        float a = b2[k];
        for (int j = 0; j < 256; j++) a = fmaf(hS[r * 256 + j], W2[j * NCLS + k], a);
        lg[o] = a;
    }
    __syncthreads();

    // log_softmax per row (warp per row, strided)
    const int w = tid >> 5, lane = tid & 31;
    for (int r = w; r < NROWS; r += 8) {
        const float a = lg[r * NCLS + lane];
        const float b = (lane < NCLS - 32) ? lg[r * NCLS + 32 + lane] : -__int_as_float(0x7f800000);
        float m = fmaxf(a, b);
#pragma unroll
        for (int o = 16; o > 0; o >>= 1) m = fmaxf(m, __shfl_xor_sync(0xffffffffu, m, o));
        float s = expf(a - m) + ((lane < NCLS - 32) ? expf(b - m) : 0.f);
#pragma unroll
        for (int o = 16; o > 0; o >>= 1) s += __shfl_xor_sync(0xffffffffu, s, o);
        const float ls = logf(s);
        out[r * NCLS + lane] = a - m - ls;
        if (lane < NCLS - 32) out[r * NCLS + 32 + lane] = b - m - ls;
    }
}

// ======================= launch ============================================
extern "C" void kernel_launch(void* const* d_in, const int* in_sizes, int n_in,
                              void* d_out, int out_size) {
    const float* pos   = (const float*)d_in[0];
    const float* Wsp   = (const float*)d_in[1];
    const float* root  = (const float*)d_in[2];
    const float* bias  = (const float*)d_in[3];
    const float* gamma = (const float*)d_in[4];
    const float* beta  = (const float*)d_in[5];
    const float* W1    = (const float*)d_in[6];
    const float* b1    = (const float*)d_in[7];
    const float* W2    = (const float*)d_in[8];
    const float* b2    = (const float*)d_in[9];
    float* out = (float*)d_out;

    knn_kernel<<<NPTS / 256, 256>>>(pos);
    geom_kernel<<<NPTS / 8, 256>>>(pos, Wsp, root, bias);
    bn_kernel<<<FDIM, 256>>>();
    ys_kernel<<<NROWS * FDIM, 256>>>(gamma, beta);
    mlp_kernel<<<1, 256>>>(W1, b1, W2, b2, out);
}

// round 7
// speedup vs baseline: 3.3339x; 1.0759x over previous
#include <cuda_runtime.h>
#include <math.h>

#define NPTS   32768          // N = B*P
#define BATCH  8
#define PPB    4096           // P
#define KNN    20             // K
#define LCOV   10             // L
#define FDIM   32             // F
#define KSV    5              // KS
#define NCLS   40
#define NROWS  24             // (N*F*3)/(P*F)

// ---------------- scratch (device globals; no allocation allowed) ----------
__device__ int   g_nbr[NPTS * KNN];
__device__ float g_node[NPTS * FDIM];
__device__ float g_v3[NPTS * 3];
__device__ float g_stats[2 * FDIM];      // [0:32) mean, [32:64) invstd
__device__ float g_part[256 * 64];       // bn partials: 256 blocks x (32 sum, 32 sumsq)
__device__ float g_ys[NROWS * FDIM];

// ======================= K1: brute-force kNN ===============================
// Two-pass, thread-per-query.
// Pass 1: maintain the 21 smallest distance keys (self included) with a
//   dependency-free FMNMX insertion: bd[i] = min(bd[i], max(s, bd[i-1])),
//   evaluated descending in-place (all reads see old values). 41 independent
//   FMNMX per insert -> issue-bound, not latency-bound.
// Pass 2: rescan; every candidate with s <= bd[KNN] is one of the 21 kept;
//   its slot is rank = #{bd[i] < s}; scatter index directly (rank 0 = self).
// Key s = |c|^2 - 2 q.c = d^2 - |q|^2 (monotone shift => same ordering).
// The key is computed through ONE intrinsic-exact helper so pass 1 and
// pass 2 agree bit-for-bit.
__device__ __forceinline__ float knn_key(float qx, float qy, float qz, float4 c) {
    float dot = __fmaf_rn(qz, c.z, __fmaf_rn(qy, c.y, __fmul_rn(qx, c.x)));
    return __fmaf_rn(-2.0f, dot, c.w);
}

__global__ __launch_bounds__(256) void knn_kernel(const float* __restrict__ pos) {
    __shared__ float  raw[768];          // coalesced staging (256 pts * 3)
    __shared__ float4 spt[256];
    const int tid  = threadIdx.x;
    const int q    = blockIdx.x * 256 + tid;          // global query index
    const int base = (blockIdx.x >> 4) * PPB;         // 16 blocks per batch

    const float qx = pos[q * 3 + 0];
    const float qy = pos[q * 3 + 1];
    const float qz = pos[q * 3 + 2];

    const float INF = __int_as_float(0x7f800000);
    float bd[KNN + 1];
#pragma unroll
    for (int i = 0; i <= KNN; i++) bd[i] = INF;
    float worst = INF;

    // ---------------- pass 1: distance keys only ----------------
    for (int t = 0; t < 16; t++) {
        {
            const int src = base * 3 + t * 768;
#pragma unroll
            for (int i = 0; i < 3; i++) raw[tid + i * 256] = pos[src + tid + i * 256];
        }
        __syncthreads();
        {
            const float cx = raw[tid * 3 + 0];
            const float cy = raw[tid * 3 + 1];
            const float cz = raw[tid * 3 + 2];
            const float w  = __fmaf_rn(cz, cz, __fmaf_rn(cy, cy, __fmul_rn(cx, cx)));
            spt[tid] = make_float4(cx, cy, cz, w);
        }
        __syncthreads();

#pragma unroll 4
        for (int jj = 0; jj < 256; jj++) {
            const float s = knn_key(qx, qy, qz, spt[jj]);
            if (s < worst) {
                // descending in-place: every bd[i-1] read is the OLD value
#pragma unroll
                for (int i = KNN; i >= 1; i--)
                    bd[i] = fminf(bd[i], fmaxf(s, bd[i - 1]));
                bd[0] = fminf(bd[0], s);
                worst = bd[KNN];
            }
        }
        __syncthreads();
    }

    // default fill: only visible if an exact-fp distance tie collides (prob ~0)
#pragma unroll
    for (int i = 0; i < KNN; i++) g_nbr[q * KNN + i] = q;

    // ---------------- pass 2: index recovery ----------------
    const float T = bd[KNN];
    for (int t = 0; t < 16; t++) {
        {
            const int src = base * 3 + t * 768;
#pragma unroll
            for (int i = 0; i < 3; i++) raw[tid + i * 256] = pos[src + tid + i * 256];
        }
        __syncthreads();
        {
            const float cx = raw[tid * 3 + 0];
            const float cy = raw[tid * 3 + 1];
            const float cz = raw[tid * 3 + 2];
            const float w  = __fmaf_rn(cz, cz, __fmaf_rn(cy, cy, __fmul_rn(cx, cx)));
            spt[tid] = make_float4(cx, cy, cz, w);
        }
        __syncthreads();

        const int tbase = base + t * 256;
#pragma unroll 4
        for (int jj = 0; jj < 256; jj++) {
            const float s = knn_key(qx, qy, qz, spt[jj]);
            if (s <= T) {
                int rank = 0;
#pragma unroll
                for (int i = 0; i < KNN; i++) rank += (bd[i] < s) ? 1 : 0;
                if (rank > 0) g_nbr[q * KNN + rank - 1] = tbase + jj;
            }
        }
        __syncthreads();
    }
}

// ======================= K2: geometry + spline conv ========================
__device__ __forceinline__ void power_iter(
    float m00, float m01, float m02, float m11, float m12, float m22,
    float& vx, float& vy, float& vz, float& lam)
{
    vx = vy = vz = 0.57735026918962576f;
#pragma unroll
    for (int it = 0; it < 5; it++) {
        float wx = m00 * vx + m01 * vy + m02 * vz;
        float wy = m01 * vx + m11 * vy + m12 * vz;
        float wz = m02 * vx + m12 * vy + m22 * vz;
        float nr = sqrtf(wx * wx + wy * wy + wz * wz) + 1e-12f;
        vx = wx / nr; vy = wy / nr; vz = wz / nr;
    }
    float wx = m00 * vx + m01 * vy + m02 * vz;
    float wy = m01 * vx + m11 * vy + m12 * vz;
    float wz = m02 * vx + m12 * vy + m22 * vz;
    lam = vx * wx + vy * wy + vz * wz;
}

// warp per point; 8 warps (8 points) per block
__global__ __launch_bounds__(256) void geom_kernel(
    const float* __restrict__ pos, const float* __restrict__ Wsp,
    const float* __restrict__ root, const float* __restrict__ bias)
{
    __shared__ float  wspS[125 * 32];
    __shared__ float  clusS[8][KNN][3];
    __shared__ float2 bfS[8][KNN * 8];     // (basis, flat-as-float)

    const int tid  = threadIdx.x;
    const int w    = tid >> 5;
    const int lane = tid & 31;
    const int n    = blockIdx.x * 8 + w;

    for (int i = tid; i < 125 * 32; i += 256) wspS[i] = Wsp[i];

    const float px = pos[n * 3 + 0];
    const float py = pos[n * 3 + 1];
    const float pz = pos[n * 3 + 2];

    if (lane < KNN) {
        const int j = g_nbr[n * KNN + lane];
        clusS[w][lane][0] = pos[j * 3 + 0] - px;
        clusS[w][lane][1] = pos[j * 3 + 1] - py;
        clusS[w][lane][2] = pos[j * 3 + 2] - pz;
    }
    __syncthreads();   // covers wspS load + cluster writes

    // covariance over first LCOV neighbors (redundant per lane; smem broadcast)
    float m00 = 0, m01 = 0, m02 = 0, m11 = 0, m12 = 0, m22 = 0;
#pragma unroll
    for (int k = 0; k < LCOV; k++) {
        const float x = clusS[w][k][0], y = clusS[w][k][1], z = clusS[w][k][2];
        m00 += x * x; m01 += x * y; m02 += x * z;
        m11 += y * y; m12 += y * z; m22 += z * z;
    }

    float e1x, e1y, e1z, lam1;
    power_iter(m00, m01, m02, m11, m12, m22, e1x, e1y, e1z, lam1);
    // deflate
    float a00 = m00 - lam1 * e1x * e1x;
    float a01 = m01 - lam1 * e1x * e1y;
    float a02 = m02 - lam1 * e1x * e1z;
    float a11 = m11 - lam1 * e1y * e1y;
    float a12 = m12 - lam1 * e1y * e1z;
    float a22 = m22 - lam1 * e1z * e1z;
    float e2x, e2y, e2z, lam2;
    power_iter(a00, a01, a02, a11, a12, a22, e2x, e2y, e2z, lam2);
    // v3 = cross(v1, v2), normalized
    float e3x = e1y * e2z - e1z * e2y;
    float e3y = e1z * e2x - e1x * e2z;
    float e3z = e1x * e2y - e1y * e2x;
    {
        float nr = sqrtf(e3x * e3x + e3y * e3y + e3z * e3z) + 1e-12f;
        e3x /= nr; e3y /= nr; e3z /= nr;
    }

    // pass over all K: sign accumulator and max|dirc|
    float sum2 = 0.f, mx01 = 0.f, mx2 = 0.f;
#pragma unroll
    for (int k = 0; k < KNN; k++) {
        const float x = clusS[w][k][0], y = clusS[w][k][1], z = clusS[w][k][2];
        const float d0 = x * e1x + y * e1y + z * e1z;
        const float d1 = x * e2x + y * e2y + z * e2z;
        const float d2 = x * e3x + y * e3y + z * e3z;
        sum2 += d2;
        mx01 = fmaxf(mx01, fmaxf(fabsf(d0), fabsf(d1)));
        mx2  = fmaxf(mx2, fabsf(d2));
    }
    const float sgn = (sum2 > 0.f) ? 1.f : ((sum2 < 0.f) ? -1.f : 0.f);
    const float mx  = fmaxf(mx01, (sgn != 0.f) ? mx2 : 0.f);

    // spline basis per neighbor (lane k handles neighbor k)
    if (lane < KNN) {
        const float x = clusS[w][lane][0], y = clusS[w][lane][1], z = clusS[w][lane][2];
        const float d0 = x * e1x + y * e1y + z * e1z;
        const float d1 = x * e2x + y * e2y + z * e2z;
        const float d2 = (x * e3x + y * e3y + z * e3z) * sgn;
        const float p0 = d0 / mx * 0.5f + 0.5f;
        const float p1 = d1 / mx * 0.5f + 0.5f;
        const float p2 = d2 / mx * 0.5f + 0.5f;
        const float v0 = p0 * 4.f, v1 = p1 * 4.f, v2 = p2 * 4.f;
        const float f0 = floorf(v0), f1 = floorf(v1), f2 = floorf(v2);
        const float r0 = v0 - f0, r1 = v1 - f1, r2 = v2 - f2;
        const int   i0 = (int)f0, i1 = (int)f1, i2 = (int)f2;
#pragma unroll
        for (int s = 0; s < 8; s++) {
            const int b0 = (s >> 2) & 1, b1v = (s >> 1) & 1, b2v = s & 1;
            const int c0 = min(max(i0 + b0, 0), KSV - 1);
            const int c1 = min(max(i1 + b1v, 0), KSV - 1);
            const int c2 = min(max(i2 + b2v, 0), KSV - 1);
            const float wgt = (b0 ? r0 : 1.f - r0) * (b1v ? r1 : 1.f - r1) * (b2v ? r2 : 1.f - r2);
            const int flat = (c0 * KSV + c1) * KSV + c2;
            bfS[w][lane * 8 + s] = make_float2(wgt, __int_as_float(flat));
        }
    }
    __syncwarp();

    // lane = feature f: accumulate msg over 160 (neighbor,corner) pairs
    float acc = 0.f;
#pragma unroll 8
    for (int e = 0; e < KNN * 8; e++) {
        const float2 t = bfS[w][e];
        acc = fmaf(t.x, wspS[__float_as_int(t.y) * 32 + lane], acc);
    }
    g_node[n * FDIM + lane] = acc / 20.0f + root[lane] + bias[lane];
    if (lane == 0) {
        g_v3[n * 3 + 0] = e3x;
        g_v3[n * 3 + 1] = e3y;
        g_v3[n * 3 + 2] = e3z;
    }
}

// ======================= K3: batchnorm stats (coalesced 2-kernel) ==========
// bn1: 256 blocks, each covers 128 points for ALL 32 features with fully
// coalesced loads; per-feature partial sum & sumsq via smem tree (strides are
// multiples of 32 so lanes keep their feature).
__global__ __launch_bounds__(256) void bn1_kernel() {
    __shared__ float sS[256], s2S[256];
    const int tid = threadIdx.x;
    const int f = tid & 31;
    const int r = tid >> 5;                 // 0..7
    const int n0 = blockIdx.x * 128;
    float s = 0.f, s2 = 0.f;
#pragma unroll
    for (int i = 0; i < 16; i++) {
        const float v = g_node[(n0 + i * 8 + r) * FDIM + f];
        s += v; s2 = fmaf(v, v, s2);
    }
    sS[tid] = s; s2S[tid] = s2; __syncthreads();
#pragma unroll
    for (int o = 128; o >= 32; o >>= 1) {
        if (tid < o) { sS[tid] += sS[tid + o]; s2S[tid] += s2S[tid + o]; }
        __syncthreads();
    }
    if (tid < 32) {
        g_part[blockIdx.x * 64 + tid]      = sS[tid];
        g_part[blockIdx.x * 64 + 32 + tid] = s2S[tid];
    }
}

// bn2: combine 256 partials per quantity in double (kills E[x^2]-mu^2 cancellation)
__global__ __launch_bounds__(64) void bn2_kernel() {
    __shared__ double tot[64];
    const int tid = threadIdx.x;            // 0..63
    double acc = 0.0;
    for (int b = 0; b < 256; b++) acc += (double)g_part[b * 64 + tid];
    tot[tid] = acc; __syncthreads();
    if (tid < 32) {
        const double mu  = tot[tid] / (double)NPTS;
        const double ex2 = tot[32 + tid] / (double)NPTS;
        const double var = ex2 - mu * mu;
        g_stats[tid]        = (float)mu;
        g_stats[FDIM + tid] = (float)(1.0 / sqrt(var + 1e-5));
    }
}

// ======================= K4: scrambled sigmoid mean -> ys ==================
// ys[r,f2] = mean_p sigmoid(xb(n,f) * v3(n,c)), with (n,f,c) recovered from
// linear = r*131072 + p*32 + f2  (the torch .view reinterpretation)
__global__ __launch_bounds__(256) void ys_kernel(
    const float* __restrict__ gamma, const float* __restrict__ beta)
{
    __shared__ float red[256];
    const int r = blockIdx.x >> 5;
    const int f2 = blockIdx.x & 31;
    const int tid = threadIdx.x;
    float s = 0.f;
    for (int p = tid; p < PPB; p += 256) {
        const int linear = r * (PPB * FDIM) + p * FDIM + f2;
        const int n   = linear / 96;
        const int rem = linear - n * 96;
        const int f   = rem / 3;
        const int c   = rem - f * 3;
        const float x  = g_node[n * FDIM + f];
        const float xb = gamma[f] * (x - g_stats[f]) * g_stats[FDIM + f] + beta[f];
        const float z  = xb * g_v3[n * 3 + c];
        s += 1.0f / (1.0f + expf(-z));
    }
    red[tid] = s; __syncthreads();
    for (int o = 128; o > 0; o >>= 1) { if (tid < o) red[tid] += red[tid + o]; __syncthreads(); }
    if (tid == 0) g_ys[blockIdx.x] = red[0] / (float)PPB;
}

// ======================= K5: MLP + log_softmax =============================
__global__ __launch_bounds__(256) void mlp_kernel(
    const float* __restrict__ W1, const float* __restrict__ b1,
    const float* __restrict__ W2, const float* __restrict__ b2,
    float* __restrict__ out)
{
    __shared__ float ysS[NROWS * FDIM];
    __shared__ float hS[NROWS * 256];
    __shared__ float lg[NROWS * NCLS];
    const int tid = threadIdx.x;

    for (int i = tid; i < NROWS * FDIM; i += 256) ysS[i] = g_ys[i];
    __syncthreads();

    // hidden layer: thread = hidden unit j
    {
        const int j = tid;
        for (int r = 0; r < NROWS; r++) {
            float a = b1[j];
#pragma unroll
            for (int f = 0; f < FDIM; f++) a = fmaf(ysS[r * FDIM + f], W1[f * 256 + j], a);
            hS[r * 256 + j] = (a > 0.f) ? a : expm1f(a);
        }
    }
    __syncthreads();

    // logits
    for (int o = tid; o < NROWS * NCLS; o += 256) {
        const int r = o / NCLS, k = o - r * NCLS;
        float a = b2[k];
        for (int j = 0; j < 256; j++) a = fmaf(hS[r * 256 + j], W2[j * NCLS + k], a);
        lg[o] = a;
    }
    __syncthreads();

    // log_softmax per row (warp per row, strided)
    const int w = tid >> 5, lane = tid & 31;
    for (int r = w; r < NROWS; r += 8) {
        const float a = lg[r * NCLS + lane];
        const float b = (lane < NCLS - 32) ? lg[r * NCLS + 32 + lane] : -__int_as_float(0x7f800000);
        float m = fmaxf(a, b);
#pragma unroll
        for (int o = 16; o > 0; o >>= 1) m = fmaxf(m, __shfl_xor_sync(0xffffffffu, m, o));
        float s = expf(a - m) + ((lane < NCLS - 32) ? expf(b - m) : 0.f);
#pragma unroll
        for (int o = 16; o > 0; o >>= 1) s += __shfl_xor_sync(0xffffffffu, s, o);
        const float ls = logf(s);
        out[r * NCLS + lane] = a - m - ls;
        if (lane < NCLS - 32) out[r * NCLS + 32 + lane] = b - m - ls;
    }
}

// ======================= launch ============================================
extern "C" void kernel_launch(void* const* d_in, const int* in_sizes, int n_in,
                              void* d_out, int out_size) {
    const float* pos   = (const float*)d_in[0];
    const float* Wsp   = (const float*)d_in[1];
    const float* root  = (const float*)d_in[2];
    const float* bias  = (const float*)d_in[3];
    const float* gamma = (const float*)d_in[4];
    const float* beta  = (const float*)d_in[5];
    const float* W1    = (const float*)d_in[6];
    const float* b1    = (const float*)d_in[7];
    const float* W2    = (const float*)d_in[8];
    const float* b2    = (const float*)d_in[9];
    float* out = (float*)d_out;

    knn_kernel<<<NPTS / 256, 256>>>(pos);
    geom_kernel<<<NPTS / 8, 256>>>(pos, Wsp, root, bias);
    bn1_kernel<<<256, 256>>>();
    bn2_kernel<<<1, 64>>>();
    ys_kernel<<<NROWS * FDIM, 256>>>(gamma, beta);
    mlp_kernel<<<1, 256>>>(W1, b1, W2, b2, out);
}

// round 9
// speedup vs baseline: 3.6001x; 1.0798x over previous
#include <cuda_runtime.h>
#include <math.h>

#define NPTS   32768          // N = B*P
#define BATCH  8
#define PPB    4096           // P
#define KNN    20             // K
#define LCOV   10             // L
#define FDIM   32             // F
#define KSV    5              // KS
#define NCLS   40
#define NROWS  24             // (N*F*3)/(P*F)

// ---------------- scratch (device globals; no allocation allowed) ----------
__device__ int   g_nbr[NPTS * KNN];
__device__ float g_node[NPTS * FDIM];
__device__ float g_v3[NPTS * 3];
__device__ float g_stats[2 * FDIM];      // [0:32) mean, [32:64) invstd
__device__ float g_part[256 * 64];       // bn partials: 256 blocks x (32 sum, 32 sumsq)
__device__ float g_ys[NROWS * FDIM];
__device__ float g_h[NROWS * 256];       // mlp hidden activations

// ======================= K1: brute-force kNN ===============================
// 4 threads per query. Each thread scans a disjoint quarter of the 4096
// candidates (4 tiles of 256), keeping the 21 smallest keys via a
// dependency-free FMNMX chain. Two shfl_xor merge rounds (1, then 2) give all
// 4 threads the identical global top-21. Pass 2 rescans each quarter and
// scatters indices by rank. Key s = |c|^2 - 2 q.c (monotone shift of d^2);
// computed via ONE intrinsic-exact helper so both passes agree bit-for-bit.
__device__ __forceinline__ float knn_key(float qx, float qy, float qz, float4 c) {
    float dot = __fmaf_rn(qz, c.z, __fmaf_rn(qy, c.y, __fmul_rn(qx, c.x)));
    return __fmaf_rn(-2.0f, dot, c.w);
}

__device__ __forceinline__ void knn_insert(float v, float (&bd)[KNN + 1]) {
    // descending in-place: every bd[i-1] read is the OLD value
#pragma unroll
    for (int i = KNN; i >= 1; i--)
        bd[i] = fminf(bd[i], fmaxf(v, bd[i - 1]));
    bd[0] = fminf(bd[0], v);
}

__global__ __launch_bounds__(256) void knn_kernel(const float* __restrict__ pos) {
    __shared__ float  raw[4 * 768];        // coalesced staging, 4 tiles
    __shared__ float4 spt[4][257];         // padded: distinct banks per buffer
    const int tid  = threadIdx.x;
    const int sub  = tid & 3;              // quarter id
    const int qi   = tid >> 2;             // query within block (0..63)
    const int q    = blockIdx.x * 64 + qi;
    const int base = (blockIdx.x >> 6) * PPB;   // 64 blocks per batch

    const float qx = pos[q * 3 + 0];
    const float qy = pos[q * 3 + 1];
    const float qz = pos[q * 3 + 2];

    const float INF = __int_as_float(0x7f800000);
    float bd[KNN + 1];
#pragma unroll
    for (int i = 0; i <= KNN; i++) bd[i] = INF;
    float worst = INF;

    // ---------------- pass 1: distance keys only ----------------
    for (int t = 0; t < 4; t++) {
        // stage tiles {t, 4+t, 8+t, 12+t} -> buffers 0..3
#pragma unroll
        for (int b = 0; b < 4; b++) {
            const int src = base * 3 + (b * 4 + t) * 768;
#pragma unroll
            for (int i = 0; i < 3; i++) raw[b * 768 + tid + i * 256] = pos[src + tid + i * 256];
        }
        __syncthreads();
#pragma unroll
        for (int b = 0; b < 4; b++) {
            const float cx = raw[b * 768 + tid * 3 + 0];
            const float cy = raw[b * 768 + tid * 3 + 1];
            const float cz = raw[b * 768 + tid * 3 + 2];
            const float w  = __fmaf_rn(cz, cz, __fmaf_rn(cy, cy, __fmul_rn(cx, cx)));
            spt[b][tid] = make_float4(cx, cy, cz, w);
        }
        __syncthreads();

#pragma unroll 4
        for (int jj = 0; jj < 256; jj++) {
            const float s = knn_key(qx, qy, qz, spt[sub][jj]);
            if (s < worst) {
                knn_insert(s, bd);
                worst = bd[KNN];
            }
        }
        __syncthreads();
    }

    // ---------------- merge the 4 per-quarter lists (identical result) ------
#pragma unroll
    for (int r = 1; r <= 2; r <<= 1) {
        float other[KNN + 1];
#pragma unroll
        for (int i = 0; i <= KNN; i++) other[i] = __shfl_xor_sync(0xffffffffu, bd[i], r);
#pragma unroll
        for (int i = 0; i <= KNN; i++) knn_insert(other[i], bd);
    }

    // default fill (only matters on exact-fp key ties; prob ~0)
    if (sub == 0) {
#pragma unroll
        for (int i = 0; i < KNN; i++) g_nbr[q * KNN + i] = q;
    }

    // ---------------- pass 2: index recovery (own quarter only) -------------
    const float T = bd[KNN];
    for (int t = 0; t < 4; t++) {
        __syncthreads();                  // also orders default-fill before writes
#pragma unroll
        for (int b = 0; b < 4; b++) {
            const int src = base * 3 + (b * 4 + t) * 768;
#pragma unroll
            for (int i = 0; i < 3; i++) raw[b * 768 + tid + i * 256] = pos[src + tid + i * 256];
        }
        __syncthreads();
#pragma unroll
        for (int b = 0; b < 4; b++) {
            const float cx = raw[b * 768 + tid * 3 + 0];
            const float cy = raw[b * 768 + tid * 3 + 1];
            const float cz = raw[b * 768 + tid * 3 + 2];
            const float w  = __fmaf_rn(cz, cz, __fmaf_rn(cy, cy, __fmul_rn(cx, cx)));
            spt[b][tid] = make_float4(cx, cy, cz, w);
        }
        __syncthreads();

        const int tbase = base + (sub * 4 + t) * 256;
#pragma unroll 4
        for (int jj = 0; jj < 256; jj++) {
            const float s = knn_key(qx, qy, qz, spt[sub][jj]);
            if (s <= T) {
                int rank = 0;
#pragma unroll
                for (int i = 0; i < KNN; i++) rank += (bd[i] < s) ? 1 : 0;
                if (rank > 0) g_nbr[q * KNN + rank - 1] = tbase + jj;
            }
        }
    }
}

// ======================= K2: geometry + spline conv ========================
__device__ __forceinline__ void power_iter(
    float m00, float m01, float m02, float m11, float m12, float m22,
    float& vx, float& vy, float& vz, float& lam)
{
    vx = vy = vz = 0.57735026918962576f;
#pragma unroll
    for (int it = 0; it < 5; it++) {
        float wx = m00 * vx + m01 * vy + m02 * vz;
        float wy = m01 * vx + m11 * vy + m12 * vz;
        float wz = m02 * vx + m12 * vy + m22 * vz;
        float nr = sqrtf(wx * wx + wy * wy + wz * wz) + 1e-12f;
        vx = wx / nr; vy = wy / nr; vz = wz / nr;
    }
    float wx = m00 * vx + m01 * vy + m02 * vz;
    float wy = m01 * vx + m11 * vy + m12 * vz;
    float wz = m02 * vx + m12 * vy + m22 * vz;
    lam = vx * wx + vy * wy + vz * wz;
}

// warp per point; 8 warps (8 points) per block
__global__ __launch_bounds__(256) void geom_kernel(
    const float* __restrict__ pos, const float* __restrict__ Wsp,
    const float* __restrict__ root, const float* __restrict__ bias)
{
    __shared__ float  wspS[125 * 32];
    __shared__ float  clusS[8][KNN][3];
    __shared__ float2 bfS[8][KNN * 8];     // (basis, flat-as-float)

    const int tid  = threadIdx.x;
    const int w    = tid >> 5;
    const int lane = tid & 31;
    const int n    = blockIdx.x * 8 + w;

    for (int i = tid; i < 125 * 32; i += 256) wspS[i] = Wsp[i];

    const float px = pos[n * 3 + 0];
    const float py = pos[n * 3 + 1];
    const float pz = pos[n * 3 + 2];

    if (lane < KNN) {
        const int j = g_nbr[n * KNN + lane];
        clusS[w][lane][0] = pos[j * 3 + 0] - px;
        clusS[w][lane][1] = pos[j * 3 + 1] - py;
        clusS[w][lane][2] = pos[j * 3 + 2] - pz;
    }
    __syncthreads();   // covers wspS load + cluster writes

    // covariance over first LCOV neighbors (redundant per lane; smem broadcast)
    float m00 = 0, m01 = 0, m02 = 0, m11 = 0, m12 = 0, m22 = 0;
#pragma unroll
    for (int k = 0; k < LCOV; k++) {
        const float x = clusS[w][k][0], y = clusS[w][k][1], z = clusS[w][k][2];
        m00 += x * x; m01 += x * y; m02 += x * z;
        m11 += y * y; m12 += y * z; m22 += z * z;
    }

    float e1x, e1y, e1z, lam1;
    power_iter(m00, m01, m02, m11, m12, m22, e1x, e1y, e1z, lam1);
    // deflate
    float a00 = m00 - lam1 * e1x * e1x;
    float a01 = m01 - lam1 * e1x * e1y;
    float a02 = m02 - lam1 * e1x * e1z;
    float a11 = m11 - lam1 * e1y * e1y;
    float a12 = m12 - lam1 * e1y * e1z;
    float a22 = m22 - lam1 * e1z * e1z;
    float e2x, e2y, e2z, lam2;
    power_iter(a00, a01, a02, a11, a12, a22, e2x, e2y, e2z, lam2);
    // v3 = cross(v1, v2), normalized
    float e3x = e1y * e2z - e1z * e2y;
    float e3y = e1z * e2x - e1x * e2z;
    float e3z = e1x * e2y - e1y * e2x;
    {
        float nr = sqrtf(e3x * e3x + e3y * e3y + e3z * e3z) + 1e-12f;
        e3x /= nr; e3y /= nr; e3z /= nr;
    }

    // pass over all K: sign accumulator and max|dirc|
    float sum2 = 0.f, mx01 = 0.f, mx2 = 0.f;
#pragma unroll
    for (int k = 0; k < KNN; k++) {
        const float x = clusS[w][k][0], y = clusS[w][k][1], z = clusS[w][k][2];
        const float d0 = x * e1x + y * e1y + z * e1z;
        const float d1 = x * e2x + y * e2y + z * e2z;
        const float d2 = x * e3x + y * e3y + z * e3z;
        sum2 += d2;
        mx01 = fmaxf(mx01, fmaxf(fabsf(d0), fabsf(d1)));
        mx2  = fmaxf(mx2, fabsf(d2));
    }
    const float sgn = (sum2 > 0.f) ? 1.f : ((sum2 < 0.f) ? -1.f : 0.f);
    const float mx  = fmaxf(mx01, (sgn != 0.f) ? mx2 : 0.f);

    // spline basis per neighbor (lane k handles neighbor k)
    if (lane < KNN) {
        const float x = clusS[w][lane][0], y = clusS[w][lane][1], z = clusS[w][lane][2];
        const float d0 = x * e1x + y * e1y + z * e1z;
        const float d1 = x * e2x + y * e2y + z * e2z;
        const float d2 = (x * e3x + y * e3y + z * e3z) * sgn;
        const float p0 = d0 / mx * 0.5f + 0.5f;
        const float p1 = d1 / mx * 0.5f + 0.5f;
        const float p2 = d2 / mx * 0.5f + 0.5f;
        const float v0 = p0 * 4.f, v1 = p1 * 4.f, v2 = p2 * 4.f;
        const float f0 = floorf(v0), f1 = floorf(v1), f2 = floorf(v2);
        const float r0 = v0 - f0, r1 = v1 - f1, r2 = v2 - f2;
        const int   i0 = (int)f0, i1 = (int)f1, i2 = (int)f2;
#pragma unroll
        for (int s = 0; s < 8; s++) {
            const int b0 = (s >> 2) & 1, b1v = (s >> 1) & 1, b2v = s & 1;
            const int c0 = min(max(i0 + b0, 0), KSV - 1);
            const int c1 = min(max(i1 + b1v, 0), KSV - 1);
            const int c2 = min(max(i2 + b2v, 0), KSV - 1);
            const float wgt = (b0 ? r0 : 1.f - r0) * (b1v ? r1 : 1.f - r1) * (b2v ? r2 : 1.f - r2);
            const int flat = (c0 * KSV + c1) * KSV + c2;
            bfS[w][lane * 8 + s] = make_float2(wgt, __int_as_float(flat));
        }
    }
    __syncwarp();

    // lane = feature f: accumulate msg over 160 (neighbor,corner) pairs
    float acc = 0.f;
#pragma unroll 8
    for (int e = 0; e < KNN * 8; e++) {
        const float2 t = bfS[w][e];
        acc = fmaf(t.x, wspS[__float_as_int(t.y) * 32 + lane], acc);
    }
    g_node[n * FDIM + lane] = acc / 20.0f + root[lane] + bias[lane];
    if (lane == 0) {
        g_v3[n * 3 + 0] = e3x;
        g_v3[n * 3 + 1] = e3y;
        g_v3[n * 3 + 2] = e3z;
    }
}

// ======================= K3: batchnorm stats (coalesced 2-kernel) ==========
__global__ __launch_bounds__(256) void bn1_kernel() {
    __shared__ float sS[256], s2S[256];
    const int tid = threadIdx.x;
    const int f = tid & 31;
    const int r = tid >> 5;                 // 0..7
    const int n0 = blockIdx.x * 128;
    float s = 0.f, s2 = 0.f;
#pragma unroll
    for (int i = 0; i < 16; i++) {
        const float v = g_node[(n0 + i * 8 + r) * FDIM + f];
        s += v; s2 = fmaf(v, v, s2);
    }
    sS[tid] = s; s2S[tid] = s2; __syncthreads();
#pragma unroll
    for (int o = 128; o >= 32; o >>= 1) {
        if (tid < o) { sS[tid] += sS[tid + o]; s2S[tid] += s2S[tid + o]; }
        __syncthreads();
    }
    if (tid < 32) {
        g_part[blockIdx.x * 64 + tid]      = sS[tid];
        g_part[blockIdx.x * 64 + 32 + tid] = s2S[tid];
    }
}

// bn2: 256 threads = 64 quantities x 4 chunks; double accumulation
__global__ __launch_bounds__(256) void bn2_kernel() {
    __shared__ double part[256];
    const int tid = threadIdx.x;
    const int quant = tid & 63;
    const int chunk = tid >> 6;             // 0..3
    double acc = 0.0;
#pragma unroll 8
    for (int b = chunk; b < 256; b += 4) acc += (double)g_part[b * 64 + quant];
    part[tid] = acc; __syncthreads();
    if (tid < 64) part[tid] = part[tid] + part[tid + 64] + part[tid + 128] + part[tid + 192];
    __syncthreads();
    if (tid < 32) {
        const double mu  = part[tid] / (double)NPTS;
        const double ex2 = part[32 + tid] / (double)NPTS;
        const double var = ex2 - mu * mu;
        g_stats[tid]        = (float)mu;
        g_stats[FDIM + tid] = (float)(1.0 / sqrt(var + 1e-5));
    }
}

// ======================= K4: scrambled sigmoid mean -> ys ==================
__global__ __launch_bounds__(256) void ys_kernel(
    const float* __restrict__ gamma, const float* __restrict__ beta)
{
    __shared__ float red[256];
    const int r = blockIdx.x >> 5;
    const int f2 = blockIdx.x & 31;
    const int tid = threadIdx.x;
    float s = 0.f;
    for (int p = tid; p < PPB; p += 256) {
        const int linear = r * (PPB * FDIM) + p * FDIM + f2;
        const int n   = linear / 96;
        const int rem = linear - n * 96;
        const int f   = rem / 3;
        const int c   = rem - f * 3;
        const float x  = g_node[n * FDIM + f];
        const float xb = gamma[f] * (x - g_stats[f]) * g_stats[FDIM + f] + beta[f];
        const float z  = xb * g_v3[n * 3 + c];
        s += 1.0f / (1.0f + expf(-z));
    }
    red[tid] = s; __syncthreads();
    for (int o = 128; o > 0; o >>= 1) { if (tid < o) red[tid] += red[tid + o]; __syncthreads(); }
    if (tid == 0) g_ys[blockIdx.x] = red[0] / (float)PPB;
}

// ======================= K5a: hidden layer (block per row) =================
__global__ __launch_bounds__(256) void mlp1_kernel(
    const float* __restrict__ W1, const float* __restrict__ b1)
{
    __shared__ float ysS[FDIM];
    const int r = blockIdx.x, j = threadIdx.x;
    if (j < FDIM) ysS[j] = g_ys[r * FDIM + j];
    __syncthreads();
    float a = b1[j];
#pragma unroll
    for (int f = 0; f < FDIM; f++) a = fmaf(ysS[f], W1[f * 256 + j], a);
    g_h[r * 256 + j] = (a > 0.f) ? a : expm1f(a);
}

// ======================= K5b: logits + log_softmax (block per row) =========
__global__ __launch_bounds__(256) void mlp2_kernel(
    const float* __restrict__ W2, const float* __restrict__ b2,
    float* __restrict__ out)
{
    __shared__ float hS[256];
    __shared__ float lg[NCLS];
    const int r = blockIdx.x, tid = threadIdx.x;
    hS[tid] = g_h[r * 256 + tid];
    __syncthreads();
    if (tid < NCLS) {
        float a = b2[tid];
#pragma unroll 8
        for (int j = 0; j < 256; j++) a = fmaf(hS[j], W2[j * NCLS + tid], a);
        lg[tid] = a;
    }
    __syncthreads();
    if (tid < 32) {
        const float a = lg[tid];
        const float b = (tid < NCLS - 32) ? lg[32 + tid] : -__int_as_float(0x7f800000);
        float m = fmaxf(a, b);
#pragma unroll
        for (int o = 16; o > 0; o >>= 1) m = fmaxf(m, __shfl_xor_sync(0xffffffffu, m, o));
        float s = expf(a - m) + ((tid < NCLS - 32) ? expf(b - m) : 0.f);
#pragma unroll
        for (int o = 16; o > 0; o >>= 1) s += __shfl_xor_sync(0xffffffffu, s, o);
        const float ls = logf(s);
        out[r * NCLS + tid] = a - m - ls;
        if (tid < NCLS - 32) out[r * NCLS + 32 + tid] = b - m - ls;
    }
}

// ======================= launch ============================================
extern "C" void kernel_launch(void* const* d_in, const int* in_sizes, int n_in,
                              void* d_out, int out_size) {
    const float* pos   = (const float*)d_in[0];
    const float* Wsp   = (const float*)d_in[1];
    const float* root  = (const float*)d_in[2];
    const float* bias  = (const float*)d_in[3];
    const float* gamma = (const float*)d_in[4];
    const float* beta  = (const float*)d_in[5];
    const float* W1    = (const float*)d_in[6];
    const float* b1    = (const float*)d_in[7];
    const float* W2    = (const float*)d_in[8];
    const float* b2    = (const float*)d_in[9];
    float* out = (float*)d_out;

    knn_kernel<<<NPTS / 64, 256>>>(pos);
    geom_kernel<<<NPTS / 8, 256>>>(pos, Wsp, root, bias);
    bn1_kernel<<<256, 256>>>();
    bn2_kernel<<<1, 256>>>();
    ys_kernel<<<NROWS * FDIM, 256>>>(gamma, beta);
    mlp1_kernel<<<NROWS, 256>>>(W1, b1);
    mlp2_kernel<<<NROWS, 256>>>(W2, b2, out);
}

// round 10
// speedup vs baseline: 7.6449x; 2.1235x over previous
#include <cuda_runtime.h>
#include <math.h>

#define NPTS   32768          // N = B*P
#define BATCH  8
#define PPB    4096           // P
#define KNN    20             // K
#define LCOV   10             // L
#define FDIM   32             // F
#define KSV    5              // KS
#define NCLS   40
#define NROWS  24             // (N*F*3)/(P*F)

// ---------------- scratch (device globals; no allocation allowed) ----------
__device__ int   g_nbr[NPTS * KNN];
__device__ float g_node[NPTS * FDIM];
__device__ float g_v3[NPTS * 3];
__device__ float g_stats[2 * FDIM];      // [0:32) mean, [32:64) invstd
__device__ float g_part[256 * 64];       // bn partials: 256 blocks x (32 sum, 32 sumsq)
__device__ float g_ys[NROWS * FDIM];
__device__ float g_h[NROWS * 256];       // mlp hidden activations

// ======================= K1: warp-cooperative kNN ==========================
// One warp per query. The top-21 list (self included; self sorts to slot 0
// since its key ~ -|q|^2 is the strict minimum) is DISTRIBUTED across lanes:
// lane i holds slot i, lane 20 holds the acceptance threshold. Each step the
// 32 lanes evaluate 32 candidates; hits (rare after warm-up) are found by
// ballot and inserted in index order via a warp-uniform loop:
//   bd'[i] = min(bd[i], max(v, bd[i-1]))   (shfl_up supplies bd[i-1])
// with indices selected alongside. Equal keys keep the incumbent (lower
// index), matching jax top_k stability. Indices ride in the list, so no
// second pass is needed. Key s = |c|^2 - 2 q.c (monotone shift of d^2).
__device__ __forceinline__ float knn_key(float qx, float qy, float qz, float4 c) {
    float dot = __fmaf_rn(qz, c.z, __fmaf_rn(qy, c.y, __fmul_rn(qx, c.x)));
    return __fmaf_rn(-2.0f, dot, c.w);
}

#define KNN_QW 16   // warps (=queries) per block

__global__ __launch_bounds__(32 * KNN_QW) void knn_kernel(const float* __restrict__ pos) {
    __shared__ float  raw[768];
    __shared__ float4 spt[256];
    const int tid  = threadIdx.x;
    const int lane = tid & 31;
    const int w    = tid >> 5;
    const int q    = blockIdx.x * KNN_QW + w;
    const int base = (q >> 12) << 12;           // batch * PPB (16 | 4096)

    const float qx = pos[q * 3 + 0];
    const float qy = pos[q * 3 + 1];
    const float qz = pos[q * 3 + 2];

    const float INF  = __int_as_float(0x7f800000);
    const float NINF = __int_as_float(0xff800000);
    float bd = INF;      // slot `lane` of the distributed list
    int   bi = -1;
    float worst = INF;   // replicated copy of slot 20

    for (int t = 0; t < 16; t++) {
        // stage 256 candidates (coalesced), precompute |c|^2
        for (int i = tid; i < 768; i += 32 * KNN_QW) raw[i] = pos[base * 3 + t * 768 + i];
        __syncthreads();
        if (tid < 256) {
            const float cx = raw[tid * 3 + 0];
            const float cy = raw[tid * 3 + 1];
            const float cz = raw[tid * 3 + 2];
            const float cw = __fmaf_rn(cz, cz, __fmaf_rn(cy, cy, __fmul_rn(cx, cx)));
            spt[tid] = make_float4(cx, cy, cz, cw);
        }
        __syncthreads();

        const int tb = base + t * 256;
#pragma unroll
        for (int s = 0; s < 8; s++) {
            const float key = knn_key(qx, qy, qz, spt[s * 32 + lane]);
            unsigned mask = __ballot_sync(0xffffffffu, key < worst);
            while (mask) {
                const int l = __ffs(mask) - 1;
                mask &= mask - 1;
                const float v = __shfl_sync(0xffffffffu, key, l);
                if (v < worst) {                       // recheck vs tightened threshold
                    const int vid = tb + s * 32 + l;
                    float prev  = __shfl_up_sync(0xffffffffu, bd, 1);
                    int   previd = __shfl_up_sync(0xffffffffu, bi, 1);
                    if (lane == 0) prev = NINF;
                    const float tmax = fmaxf(v, prev);
                    const int   tmid = (v >= prev) ? vid : previd;
                    const bool  keep = (bd <= tmax);   // equal keys keep incumbent
                    bi = keep ? bi : tmid;
                    bd = keep ? bd : tmax;
                    worst = __shfl_sync(0xffffffffu, bd, 20);
                }
            }
        }
        __syncthreads();
    }

    // slot 0 = self; emit slots 1..20
    if (lane >= 1 && lane <= KNN) g_nbr[q * KNN + lane - 1] = bi;
}

// ======================= K2: geometry + spline conv ========================
__device__ __forceinline__ void power_iter(
    float m00, float m01, float m02, float m11, float m12, float m22,
    float& vx, float& vy, float& vz, float& lam)
{
    vx = vy = vz = 0.57735026918962576f;
#pragma unroll
    for (int it = 0; it < 5; it++) {
        float wx = m00 * vx + m01 * vy + m02 * vz;
        float wy = m01 * vx + m11 * vy + m12 * vz;
        float wz = m02 * vx + m12 * vy + m22 * vz;
        float nr = sqrtf(wx * wx + wy * wy + wz * wz) + 1e-12f;
        vx = wx / nr; vy = wy / nr; vz = wz / nr;
    }
    float wx = m00 * vx + m01 * vy + m02 * vz;
    float wy = m01 * vx + m11 * vy + m12 * vz;
    float wz = m02 * vx + m12 * vy + m22 * vz;
    lam = vx * wx + vy * wy + vz * wz;
}

// warp per point; 8 warps (8 points) per block
__global__ __launch_bounds__(256) void geom_kernel(
    const float* __restrict__ pos, const float* __restrict__ Wsp,
    const float* __restrict__ root, const float* __restrict__ bias)
{
    __shared__ float  wspS[125 * 32];
    __shared__ float  clusS[8][KNN][3];
    __shared__ float2 bfS[8][KNN * 8];     // (basis, flat-as-float)

    const int tid  = threadIdx.x;
    const int w    = tid >> 5;
    const int lane = tid & 31;
    const int n    = blockIdx.x * 8 + w;

    for (int i = tid; i < 125 * 32; i += 256) wspS[i] = Wsp[i];

    const float px = pos[n * 3 + 0];
    const float py = pos[n * 3 + 1];
    const float pz = pos[n * 3 + 2];

    if (lane < KNN) {
        const int j = g_nbr[n * KNN + lane];
        clusS[w][lane][0] = pos[j * 3 + 0] - px;
        clusS[w][lane][1] = pos[j * 3 + 1] - py;
        clusS[w][lane][2] = pos[j * 3 + 2] - pz;
    }
    __syncthreads();   // covers wspS load + cluster writes

    // covariance over first LCOV neighbors (redundant per lane; smem broadcast)
    float m00 = 0, m01 = 0, m02 = 0, m11 = 0, m12 = 0, m22 = 0;
#pragma unroll
    for (int k = 0; k < LCOV; k++) {
        const float x = clusS[w][k][0], y = clusS[w][k][1], z = clusS[w][k][2];
        m00 += x * x; m01 += x * y; m02 += x * z;
        m11 += y * y; m12 += y * z; m22 += z * z;
    }

    float e1x, e1y, e1z, lam1;
    power_iter(m00, m01, m02, m11, m12, m22, e1x, e1y, e1z, lam1);
    // deflate
    float a00 = m00 - lam1 * e1x * e1x;
    float a01 = m01 - lam1 * e1x * e1y;
    float a02 = m02 - lam1 * e1x * e1z;
    float a11 = m11 - lam1 * e1y * e1y;
    float a12 = m12 - lam1 * e1y * e1z;
    float a22 = m22 - lam1 * e1z * e1z;
    float e2x, e2y, e2z, lam2;
    power_iter(a00, a01, a02, a11, a12, a22, e2x, e2y, e2z, lam2);
    // v3 = cross(v1, v2), normalized
    float e3x = e1y * e2z - e1z * e2y;
    float e3y = e1z * e2x - e1x * e2z;
    float e3z = e1x * e2y - e1y * e2x;
    {
        float nr = sqrtf(e3x * e3x + e3y * e3y + e3z * e3z) + 1e-12f;
        e3x /= nr; e3y /= nr; e3z /= nr;
    }

    // pass over all K: sign accumulator and max|dirc|
    float sum2 = 0.f, mx01 = 0.f, mx2 = 0.f;
#pragma unroll
    for (int k = 0; k < KNN; k++) {
        const float x = clusS[w][k][0], y = clusS[w][k][1], z = clusS[w][k][2];
        const float d0 = x * e1x + y * e1y + z * e1z;
        const float d1 = x * e2x + y * e2y + z * e2z;
        const float d2 = x * e3x + y * e3y + z * e3z;
        sum2 += d2;
        mx01 = fmaxf(mx01, fmaxf(fabsf(d0), fabsf(d1)));
        mx2  = fmaxf(mx2, fabsf(d2));
    }
    const float sgn = (sum2 > 0.f) ? 1.f : ((sum2 < 0.f) ? -1.f : 0.f);
    const float mx  = fmaxf(mx01, (sgn != 0.f) ? mx2 : 0.f);

    // spline basis per neighbor (lane k handles neighbor k)
    if (lane < KNN) {
        const float x = clusS[w][lane][0], y = clusS[w][lane][1], z = clusS[w][lane][2];
        const float d0 = x * e1x + y * e1y + z * e1z;
        const float d1 = x * e2x + y * e2y + z * e2z;
        const float d2 = (x * e3x + y * e3y + z * e3z) * sgn;
        const float p0 = d0 / mx * 0.5f + 0.5f;
        const float p1 = d1 / mx * 0.5f + 0.5f;
        const float p2 = d2 / mx * 0.5f + 0.5f;
        const float v0 = p0 * 4.f, v1 = p1 * 4.f, v2 = p2 * 4.f;
        const float f0 = floorf(v0), f1 = floorf(v1), f2 = floorf(v2);
        const float r0 = v0 - f0, r1 = v1 - f1, r2 = v2 - f2;
        const int   i0 = (int)f0, i1 = (int)f1, i2 = (int)f2;
#pragma unroll
        for (int s = 0; s < 8; s++) {
            const int b0 = (s >> 2) & 1, b1v = (s >> 1) & 1, b2v = s & 1;
            const int c0 = min(max(i0 + b0, 0), KSV - 1);
            const int c1 = min(max(i1 + b1v, 0), KSV - 1);
            const int c2 = min(max(i2 + b2v, 0), KSV - 1);
            const float wgt = (b0 ? r0 : 1.f - r0) * (b1v ? r1 : 1.f - r1) * (b2v ? r2 : 1.f - r2);
            const int flat = (c0 * KSV + c1) * KSV + c2;
            bfS[w][lane * 8 + s] = make_float2(wgt, __int_as_float(flat));
        }
    }
    __syncwarp();

    // lane = feature f: accumulate msg over 160 (neighbor,corner) pairs
    float acc = 0.f;
#pragma unroll 8
    for (int e = 0; e < KNN * 8; e++) {
        const float2 t = bfS[w][e];
        acc = fmaf(t.x, wspS[__float_as_int(t.y) * 32 + lane], acc);
    }
    g_node[n * FDIM + lane] = acc / 20.0f + root[lane] + bias[lane];
    if (lane == 0) {
        g_v3[n * 3 + 0] = e3x;
        g_v3[n * 3 + 1] = e3y;
        g_v3[n * 3 + 2] = e3z;
    }
}

// ======================= K3: batchnorm stats (coalesced 2-kernel) ==========
__global__ __launch_bounds__(256) void bn1_kernel() {
    __shared__ float sS[256], s2S[256];
    const int tid = threadIdx.x;
    const int f = tid & 31;
    const int r = tid >> 5;                 // 0..7
    const int n0 = blockIdx.x * 128;
    float s = 0.f, s2 = 0.f;
#pragma unroll
    for (int i = 0; i < 16; i++) {
        const float v = g_node[(n0 + i * 8 + r) * FDIM + f];
        s += v; s2 = fmaf(v, v, s2);
    }
    sS[tid] = s; s2S[tid] = s2; __syncthreads();
#pragma unroll
    for (int o = 128; o >= 32; o >>= 1) {
        if (tid < o) { sS[tid] += sS[tid + o]; s2S[tid] += s2S[tid + o]; }
        __syncthreads();
    }
    if (tid < 32) {
        g_part[blockIdx.x * 64 + tid]      = sS[tid];
        g_part[blockIdx.x * 64 + 32 + tid] = s2S[tid];
    }
}

// bn2: 256 threads = 64 quantities x 4 chunks; double accumulation
__global__ __launch_bounds__(256) void bn2_kernel() {
    __shared__ double part[256];
    const int tid = threadIdx.x;
    const int quant = tid & 63;
    const int chunk = tid >> 6;             // 0..3
    double acc = 0.0;
#pragma unroll 8
    for (int b = chunk; b < 256; b += 4) acc += (double)g_part[b * 64 + quant];
    part[tid] = acc; __syncthreads();
    if (tid < 64) part[tid] = part[tid] + part[tid + 64] + part[tid + 128] + part[tid + 192];
    __syncthreads();
    if (tid < 32) {
        const double mu  = part[tid] / (double)NPTS;
        const double ex2 = part[32 + tid] / (double)NPTS;
        const double var = ex2 - mu * mu;
        g_stats[tid]        = (float)mu;
        g_stats[FDIM + tid] = (float)(1.0 / sqrt(var + 1e-5));
    }
}

// ======================= K4: scrambled sigmoid mean -> ys ==================
__global__ __launch_bounds__(256) void ys_kernel(
    const float* __restrict__ gamma, const float* __restrict__ beta)
{
    __shared__ float red[256];
    const int r = blockIdx.x >> 5;
    const int f2 = blockIdx.x & 31;
    const int tid = threadIdx.x;
    float s = 0.f;
    for (int p = tid; p < PPB; p += 256) {
        const int linear = r * (PPB * FDIM) + p * FDIM + f2;
        const int n   = linear / 96;
        const int rem = linear - n * 96;
        const int f   = rem / 3;
        const int c   = rem - f * 3;
        const float x  = g_node[n * FDIM + f];
        const float xb = gamma[f] * (x - g_stats[f]) * g_stats[FDIM + f] + beta[f];
        const float z  = xb * g_v3[n * 3 + c];
        s += 1.0f / (1.0f + expf(-z));
    }
    red[tid] = s; __syncthreads();
    for (int o = 128; o > 0; o >>= 1) { if (tid < o) red[tid] += red[tid + o]; __syncthreads(); }
    if (tid == 0) g_ys[blockIdx.x] = red[0] / (float)PPB;
}

// ======================= K5a: hidden layer (block per row) =================
__global__ __launch_bounds__(256) void mlp1_kernel(
    const float* __restrict__ W1, const float* __restrict__ b1)
{
    __shared__ float ysS[FDIM];
    const int r = blockIdx.x, j = threadIdx.x;
    if (j < FDIM) ysS[j] = g_ys[r * FDIM + j];
    __syncthreads();
    float a = b1[j];
#pragma unroll
    for (int f = 0; f < FDIM; f++) a = fmaf(ysS[f], W1[f * 256 + j], a);
    g_h[r * 256 + j] = (a > 0.f) ? a : expm1f(a);
}

// ======================= K5b: logits + log_softmax (block per row) =========
__global__ __launch_bounds__(256) void mlp2_kernel(
    const float* __restrict__ W2, const float* __restrict__ b2,
    float* __restrict__ out)
{
    __shared__ float hS[256];
    __shared__ float lg[NCLS];
    const int r = blockIdx.x, tid = threadIdx.x;
    hS[tid] = g_h[r * 256 + tid];
    __syncthreads();
    if (tid < NCLS) {
        float a = b2[tid];
#pragma unroll 8
        for (int j = 0; j < 256; j++) a = fmaf(hS[j], W2[j * NCLS + tid], a);
        lg[tid] = a;
    }
    __syncthreads();
    if (tid < 32) {
        const float a = lg[tid];
        const float b = (tid < NCLS - 32) ? lg[32 + tid] : -__int_as_float(0x7f800000);
        float m = fmaxf(a, b);
#pragma unroll
        for (int o = 16; o > 0; o >>= 1) m = fmaxf(m, __shfl_xor_sync(0xffffffffu, m, o));
        float s = expf(a - m) + ((tid < NCLS - 32) ? expf(b - m) : 0.f);
#pragma unroll
        for (int o = 16; o > 0; o >>= 1) s += __shfl_xor_sync(0xffffffffu, s, o);
        const float ls = logf(s);
        out[r * NCLS + tid] = a - m - ls;
        if (tid < NCLS - 32) out[r * NCLS + 32 + tid] = b - m - ls;
    }
}

// ======================= launch ============================================
extern "C" void kernel_launch(void* const* d_in, const int* in_sizes, int n_in,
                              void* d_out, int out_size) {
    const float* pos   = (const float*)d_in[0];
    const float* Wsp   = (const float*)d_in[1];
    const float* root  = (const float*)d_in[2];
    const float* bias  = (const float*)d_in[3];
    const float* gamma = (const float*)d_in[4];
    const float* beta  = (const float*)d_in[5];
    const float* W1    = (const float*)d_in[6];
    const float* b1    = (const float*)d_in[7];
    const float* W2    = (const float*)d_in[8];
    const float* b2    = (const float*)d_in[9];
    float* out = (float*)d_out;

    knn_kernel<<<NPTS / KNN_QW, 32 * KNN_QW>>>(pos);
    geom_kernel<<<NPTS / 8, 256>>>(pos, Wsp, root, bias);
    bn1_kernel<<<256, 256>>>();
    bn2_kernel<<<1, 256>>>();
    ys_kernel<<<NROWS * FDIM, 256>>>(gamma, beta);
    mlp1_kernel<<<NROWS, 256>>>(W1, b1);
    mlp2_kernel<<<NROWS, 256>>>(W2, b2, out);
}

// round 11
// speedup vs baseline: 8.2898x; 1.0843x over previous
#include <cuda_runtime.h>
#include <math.h>

#define NPTS   32768          // N = B*P
#define BATCH  8
#define PPB    4096           // P
#define KNN    20             // K
#define LCOV   10             // L
#define FDIM   32             // F
#define KSV    5              // KS
#define NCLS   40
#define NROWS  24             // (N*F*3)/(P*F)

// ---------------- scratch (device globals; no allocation allowed) ----------
__device__ float4 g_pos4[NPTS];          // (x,y,z,|p|^2)
__device__ int    g_nbr[NPTS * KNN];
__device__ float  g_node[NPTS * FDIM];
__device__ float  g_v3[NPTS * 3];
__device__ float  g_stats[2 * FDIM];     // [0:32) mean, [32:64) invstd
__device__ float  g_part[256 * 64];      // bn partials
__device__ unsigned g_bn_count;          // zero-init; reset by finalizer
__device__ float  g_ys[NROWS * FDIM];

// ======================= K0: pos4 precompute ===============================
__global__ __launch_bounds__(256) void pos4_kernel(const float* __restrict__ pos) {
    const int i = blockIdx.x * 256 + threadIdx.x;
    const float cx = pos[i * 3 + 0];
    const float cy = pos[i * 3 + 1];
    const float cz = pos[i * 3 + 2];
    const float cw = __fmaf_rn(cz, cz, __fmaf_rn(cy, cy, __fmul_rn(cx, cx)));
    g_pos4[i] = make_float4(cx, cy, cz, cw);
}

// ======================= K1: warp-cooperative kNN ==========================
// One warp per query; no smem, no barriers. Top-21 list (self = slot 0, key
// ~ -|q|^2 strict minimum) distributed across lanes: lane i holds slot i,
// slot 20 = acceptance threshold. Fast path: 128 candidates per round
// (4 keys/lane, folded via fminf, ONE any_sync). Slow path: per-key ballots
// + shfl insert chain, candidates in ascending index (tie behavior = serial
// scan = jax top_k stability). Key s = |c|^2 - 2 q.c (monotone shift of d^2).
__device__ __forceinline__ float knn_key(float qx, float qy, float qz, float4 c) {
    float dot = __fmaf_rn(qz, c.z, __fmaf_rn(qy, c.y, __fmul_rn(qx, c.x)));
    return __fmaf_rn(-2.0f, dot, c.w);
}

__global__ __launch_bounds__(256) void knn_kernel() {
    const int lane = threadIdx.x & 31;
    const int w    = threadIdx.x >> 5;
    const int q    = blockIdx.x * 8 + w;
    const int base = (q >> 12) << 12;           // batch * PPB

    const float4 qp = g_pos4[q];
    const float qx = qp.x, qy = qp.y, qz = qp.z;

    const float INF  = __int_as_float(0x7f800000);
    const float NINF = __int_as_float(0xff800000);
    float bd = INF;      // slot `lane` of the distributed list
    int   bi = -1;
    float worst = INF;   // replicated copy of slot 20

    const float4* __restrict__ bp = g_pos4 + base;

    for (int r = 0; r < 32; r++) {
        const int rb = r * 128;
        float kk[4];
        kk[0] = knn_key(qx, qy, qz, bp[rb + lane]);
        kk[1] = knn_key(qx, qy, qz, bp[rb + 32 + lane]);
        kk[2] = knn_key(qx, qy, qz, bp[rb + 64 + lane]);
        kk[3] = knn_key(qx, qy, qz, bp[rb + 96 + lane]);
        const float kmin = fminf(fminf(kk[0], kk[1]), fminf(kk[2], kk[3]));
        if (__any_sync(0xffffffffu, kmin < worst)) {
#pragma unroll
            for (int j = 0; j < 4; j++) {
                unsigned mask = __ballot_sync(0xffffffffu, kk[j] < worst);
                while (mask) {
                    const int l = __ffs(mask) - 1;
                    mask &= mask - 1;
                    const float v = __shfl_sync(0xffffffffu, kk[j], l);
                    if (v < worst) {               // recheck vs tightened threshold
                        const int vid = base + rb + j * 32 + l;
                        float prev   = __shfl_up_sync(0xffffffffu, bd, 1);
                        int   previd = __shfl_up_sync(0xffffffffu, bi, 1);
                        if (lane == 0) prev = NINF;
                        const float tmax = fmaxf(v, prev);
                        const int   tmid = (v >= prev) ? vid : previd;
                        const bool  keep = (bd <= tmax);   // equal keys keep incumbent
                        bi = keep ? bi : tmid;
                        bd = keep ? bd : tmax;
                        worst = __shfl_sync(0xffffffffu, bd, 20);
                    }
                }
            }
        }
    }

    // slot 0 = self; emit slots 1..20
    if (lane >= 1 && lane <= KNN) g_nbr[q * KNN + lane - 1] = bi;
}

// ======================= K2: geometry + spline conv ========================
__device__ __forceinline__ void power_iter(
    float m00, float m01, float m02, float m11, float m12, float m22,
    float& vx, float& vy, float& vz, float& lam)
{
    vx = vy = vz = 0.57735026918962576f;
#pragma unroll
    for (int it = 0; it < 5; it++) {
        float wx = m00 * vx + m01 * vy + m02 * vz;
        float wy = m01 * vx + m11 * vy + m12 * vz;
        float wz = m02 * vx + m12 * vy + m22 * vz;
        float nr = sqrtf(wx * wx + wy * wy + wz * wz) + 1e-12f;
        vx = wx / nr; vy = wy / nr; vz = wz / nr;
    }
    float wx = m00 * vx + m01 * vy + m02 * vz;
    float wy = m01 * vx + m11 * vy + m12 * vz;
    float wz = m02 * vx + m12 * vy + m22 * vz;
    lam = vx * wx + vy * wy + vz * wz;
}

// warp per point; 8 warps (8 points) per block
__global__ __launch_bounds__(256) void geom_kernel(
    const float* __restrict__ pos, const float* __restrict__ Wsp,
    const float* __restrict__ root, const float* __restrict__ bias)
{
    __shared__ float  wspS[125 * 32];
    __shared__ float  clusS[8][KNN][3];
    __shared__ float2 bfS[8][KNN * 8];     // (basis, flat-as-float)

    const int tid  = threadIdx.x;
    const int w    = tid >> 5;
    const int lane = tid & 31;
    const int n    = blockIdx.x * 8 + w;

    for (int i = tid; i < 125 * 32; i += 256) wspS[i] = Wsp[i];

    const float px = pos[n * 3 + 0];
    const float py = pos[n * 3 + 1];
    const float pz = pos[n * 3 + 2];

    if (lane < KNN) {
        const int j = g_nbr[n * KNN + lane];
        clusS[w][lane][0] = pos[j * 3 + 0] - px;
        clusS[w][lane][1] = pos[j * 3 + 1] - py;
        clusS[w][lane][2] = pos[j * 3 + 2] - pz;
    }
    __syncthreads();   // covers wspS load + cluster writes

    // covariance over first LCOV neighbors (redundant per lane; smem broadcast)
    float m00 = 0, m01 = 0, m02 = 0, m11 = 0, m12 = 0, m22 = 0;
#pragma unroll
    for (int k = 0; k < LCOV; k++) {
        const float x = clusS[w][k][0], y = clusS[w][k][1], z = clusS[w][k][2];
        m00 += x * x; m01 += x * y; m02 += x * z;
        m11 += y * y; m12 += y * z; m22 += z * z;
    }

    float e1x, e1y, e1z, lam1;
    power_iter(m00, m01, m02, m11, m12, m22, e1x, e1y, e1z, lam1);
    // deflate
    float a00 = m00 - lam1 * e1x * e1x;
    float a01 = m01 - lam1 * e1x * e1y;
    float a02 = m02 - lam1 * e1x * e1z;
    float a11 = m11 - lam1 * e1y * e1y;
    float a12 = m12 - lam1 * e1y * e1z;
    float a22 = m22 - lam1 * e1z * e1z;
    float e2x, e2y, e2z, lam2;
    power_iter(a00, a01, a02, a11, a12, a22, e2x, e2y, e2z, lam2);
    // v3 = cross(v1, v2), normalized
    float e3x = e1y * e2z - e1z * e2y;
    float e3y = e1z * e2x - e1x * e2z;
    float e3z = e1x * e2y - e1y * e2x;
    {
        float nr = sqrtf(e3x * e3x + e3y * e3y + e3z * e3z) + 1e-12f;
        e3x /= nr; e3y /= nr; e3z /= nr;
    }

    // pass over all K: sign accumulator and max|dirc|
    float sum2 = 0.f, mx01 = 0.f, mx2 = 0.f;
#pragma unroll
    for (int k = 0; k < KNN; k++) {
        const float x = clusS[w][k][0], y = clusS[w][k][1], z = clusS[w][k][2];
        const float d0 = x * e1x + y * e1y + z * e1z;
        const float d1 = x * e2x + y * e2y + z * e2z;
        const float d2 = x * e3x + y * e3y + z * e3z;
        sum2 += d2;
        mx01 = fmaxf(mx01, fmaxf(fabsf(d0), fabsf(d1)));
        mx2  = fmaxf(mx2, fabsf(d2));
    }
    const float sgn = (sum2 > 0.f) ? 1.f : ((sum2 < 0.f) ? -1.f : 0.f);
    const float mx  = fmaxf(mx01, (sgn != 0.f) ? mx2 : 0.f);

    // spline basis per neighbor (lane k handles neighbor k)
    if (lane < KNN) {
        const float x = clusS[w][lane][0], y = clusS[w][lane][1], z = clusS[w][lane][2];
        const float d0 = x * e1x + y * e1y + z * e1z;
        const float d1 = x * e2x + y * e2y + z * e2z;
        const float d2 = (x * e3x + y * e3y + z * e3z) * sgn;
        const float p0 = d0 / mx * 0.5f + 0.5f;
        const float p1 = d1 / mx * 0.5f + 0.5f;
        const float p2 = d2 / mx * 0.5f + 0.5f;
        const float v0 = p0 * 4.f, v1 = p1 * 4.f, v2 = p2 * 4.f;
        const float f0 = floorf(v0), f1 = floorf(v1), f2 = floorf(v2);
        const float r0 = v0 - f0, r1 = v1 - f1, r2 = v2 - f2;
        const int   i0 = (int)f0, i1 = (int)f1, i2 = (int)f2;
#pragma unroll
        for (int s = 0; s < 8; s++) {
            const int b0 = (s >> 2) & 1, b1v = (s >> 1) & 1, b2v = s & 1;
            const int c0 = min(max(i0 + b0, 0), KSV - 1);
            const int c1 = min(max(i1 + b1v, 0), KSV - 1);
            const int c2 = min(max(i2 + b2v, 0), KSV - 1);
            const float wgt = (b0 ? r0 : 1.f - r0) * (b1v ? r1 : 1.f - r1) * (b2v ? r2 : 1.f - r2);
            const int flat = (c0 * KSV + c1) * KSV + c2;
            bfS[w][lane * 8 + s] = make_float2(wgt, __int_as_float(flat));
        }
    }
    __syncwarp();

    // lane = feature f: accumulate msg over 160 (neighbor,corner) pairs
    float acc = 0.f;
#pragma unroll 8
    for (int e = 0; e < KNN * 8; e++) {
        const float2 t = bfS[w][e];
        acc = fmaf(t.x, wspS[__float_as_int(t.y) * 32 + lane], acc);
    }
    g_node[n * FDIM + lane] = acc / 20.0f + root[lane] + bias[lane];
    if (lane == 0) {
        g_v3[n * 3 + 0] = e3x;
        g_v3[n * 3 + 1] = e3y;
        g_v3[n * 3 + 2] = e3z;
    }
}

// ======================= K3: batchnorm stats (fused, last-block finalize) ==
__global__ __launch_bounds__(256) void bn_kernel() {
    __shared__ float sS[256], s2S[256];
    const int tid = threadIdx.x;
    const int f = tid & 31;
    const int r = tid >> 5;                 // 0..7
    const int n0 = blockIdx.x * 128;
    float s = 0.f, s2 = 0.f;
#pragma unroll
    for (int i = 0; i < 16; i++) {
        const float v = g_node[(n0 + i * 8 + r) * FDIM + f];
        s += v; s2 = fmaf(v, v, s2);
    }
    sS[tid] = s; s2S[tid] = s2; __syncthreads();
#pragma unroll
    for (int o = 128; o >= 32; o >>= 1) {
        if (tid < o) { sS[tid] += sS[tid + o]; s2S[tid] += s2S[tid + o]; }
        __syncthreads();
    }
    if (tid < 32) {
        g_part[blockIdx.x * 64 + tid]      = sS[tid];
        g_part[blockIdx.x * 64 + 32 + tid] = s2S[tid];
    }

    // last block finalizes (threadfence-reduction pattern)
    __shared__ unsigned lastS;
    __threadfence();
    if (tid == 0) lastS = (atomicAdd(&g_bn_count, 1u) == 255u) ? 1u : 0u;
    __syncthreads();
    if (lastS) {
        __shared__ double part[256];
        const int quant = tid & 63;
        const int chunk = tid >> 6;         // 0..3
        double acc = 0.0;
#pragma unroll 8
        for (int b = chunk; b < 256; b += 4) acc += (double)g_part[b * 64 + quant];
        part[tid] = acc; __syncthreads();
        if (tid < 64) part[tid] = part[tid] + part[tid + 64] + part[tid + 128] + part[tid + 192];
        __syncthreads();
        if (tid < 32) {
            const double mu  = part[tid] / (double)NPTS;
            const double ex2 = part[32 + tid] / (double)NPTS;
            const double var = ex2 - mu * mu;
            g_stats[tid]        = (float)mu;
            g_stats[FDIM + tid] = (float)(1.0 / sqrt(var + 1e-5));
        }
        if (tid == 0) g_bn_count = 0;       // reset for graph replay
    }
}

// ======================= K4: scrambled sigmoid mean -> ys ==================
__global__ __launch_bounds__(256) void ys_kernel(
    const float* __restrict__ gamma, const float* __restrict__ beta)
{
    __shared__ float red[256];
    const int r = blockIdx.x >> 5;
    const int f2 = blockIdx.x & 31;
    const int tid = threadIdx.x;
    float s = 0.f;
    for (int p = tid; p < PPB; p += 256) {
        const int linear = r * (PPB * FDIM) + p * FDIM + f2;
        const int n   = linear / 96;
        const int rem = linear - n * 96;
        const int f   = rem / 3;
        const int c   = rem - f * 3;
        const float x  = g_node[n * FDIM + f];
        const float xb = gamma[f] * (x - g_stats[f]) * g_stats[FDIM + f] + beta[f];
        const float z  = xb * g_v3[n * 3 + c];
        s += 1.0f / (1.0f + expf(-z));
    }
    red[tid] = s; __syncthreads();
    for (int o = 128; o > 0; o >>= 1) { if (tid < o) red[tid] += red[tid + o]; __syncthreads(); }
    if (tid == 0) g_ys[blockIdx.x] = red[0] / (float)PPB;
}

// ======================= K5: fused MLP + log_softmax (block per row) =======
__global__ __launch_bounds__(256) void mlp_kernel(
    const float* __restrict__ W1, const float* __restrict__ b1,
    const float* __restrict__ W2, const float* __restrict__ b2,
    float* __restrict__ out)
{
    __shared__ float ysS[FDIM];
    __shared__ float hS[256];
    __shared__ float lg[NCLS];
    const int r = blockIdx.x, tid = threadIdx.x;

    if (tid < FDIM) ysS[tid] = g_ys[r * FDIM + tid];
    __syncthreads();

    {   // hidden unit j = tid
        float a = b1[tid];
#pragma unroll
        for (int f = 0; f < FDIM; f++) a = fmaf(ysS[f], W1[f * 256 + tid], a);
        hS[tid] = (a > 0.f) ? a : expm1f(a);
    }
    __syncthreads();

    if (tid < NCLS) {
        float a = b2[tid];
#pragma unroll 8
        for (int j = 0; j < 256; j++) a = fmaf(hS[j], W2[j * NCLS + tid], a);
        lg[tid] = a;
    }
    __syncthreads();

    if (tid < 32) {
        const float a = lg[tid];
        const float b = (tid < NCLS - 32) ? lg[32 + tid] : -__int_as_float(0x7f800000);
        float m = fmaxf(a, b);
#pragma unroll
        for (int o = 16; o > 0; o >>= 1) m = fmaxf(m, __shfl_xor_sync(0xffffffffu, m, o));
        float s = expf(a - m) + ((tid < NCLS - 32) ? expf(b - m) : 0.f);
#pragma unroll
        for (int o = 16; o > 0; o >>= 1) s += __shfl_xor_sync(0xffffffffu, s, o);
        const float ls = logf(s);
        out[r * NCLS + tid] = a - m - ls;
        if (tid < NCLS - 32) out[r * NCLS + 32 + tid] = b - m - ls;
    }
}

// ======================= launch ============================================
extern "C" void kernel_launch(void* const* d_in, const int* in_sizes, int n_in,
                              void* d_out, int out_size) {
    const float* pos   = (const float*)d_in[0];
    const float* Wsp   = (const float*)d_in[1];
    const float* root  = (const float*)d_in[2];
    const float* bias  = (const float*)d_in[3];
    const float* gamma = (const float*)d_in[4];
    const float* beta  = (const float*)d_in[5];
    const float* W1    = (const float*)d_in[6];
    const float* b1    = (const float*)d_in[7];
    const float* W2    = (const float*)d_in[8];
    const float* b2    = (const float*)d_in[9];
    float* out = (float*)d_out;

    pos4_kernel<<<NPTS / 256, 256>>>(pos);
    knn_kernel<<<NPTS / 8, 256>>>();
    geom_kernel<<<NPTS / 8, 256>>>(pos, Wsp, root, bias);
    bn_kernel<<<256, 256>>>();
    ys_kernel<<<NROWS * FDIM, 256>>>(gamma, beta);
    mlp_kernel<<<NROWS, 256>>>(W1, b1, W2, b2, out);
}